// round 10
// baseline (speedup 1.0000x reference)
#include <cuda_runtime.h>
#include <stdint.h>

#define KPRE       500
#define MAXDET     300
#define SCORE_THR  0.05f
#define NMS_THR    0.5f
#define MIN_SIZE   0.01f
#define BBOX_CLAMP 4.135166556742356f   // log(1000/16)
#define AREA_SCALE (NMS_THR / (1.0f + NMS_THR))   // thr/(1+thr)

#define HLO        0.99f
#define HBINS      64
#define HSCALE     6400.0f               // HBINS / (1 - HLO)
#define CAPG       16384
#define KMAX       2048
#define FBINS      8192

#define NTN        512
// dynamic smem layout for fused nms:
//   [0, 32768)      ioum (32000B used) | fhist (fallback, 32768B)  [aliased]
//   [32768, 49152)  keys [KMAX]
//   [49152, 57344)  cbox [512] float4
#define DYN_SMEM   57344

#define BMAX   2
#define AMAX   131072
#define CMAX   96
#define BCMAX  192

__device__ float              g_boxes[(size_t)BMAX * AMAX * 4];
__device__ unsigned char      g_valid[(size_t)BMAX * AMAX];
__device__ unsigned long long g_keys[(size_t)BCMAX * CAPG];
__device__ unsigned int       g_cnt[BCMAX];

// ---------------------------------------------------------------------------
// K1: decode + clamp + valid mask; zero per-class counters
// ---------------------------------------------------------------------------
__global__ void rn_decode(const float* __restrict__ deltas,
                          const float* __restrict__ anchors,
                          const int* __restrict__ imh,
                          const int* __restrict__ imw,
                          int B, int A) {
    int i = blockIdx.x * blockDim.x + threadIdx.x;
    if (i < BCMAX) g_cnt[i] = 0;
    if (i >= B * A) return;
    float W = (float)imw[0];
    float H = (float)imh[0];
    float4 an = reinterpret_cast<const float4*>(anchors)[i];
    float4 dt = reinterpret_cast<const float4*>(deltas)[i];
    float aw  = an.z - an.x;
    float ah  = an.w - an.y;
    float acx = an.x + 0.5f * aw;
    float acy = an.y + 0.5f * ah;
    float dw  = fminf(dt.z, BBOX_CLAMP);
    float dh  = fminf(dt.w, BBOX_CLAMP);
    float pcx = dt.x * aw + acx;
    float pcy = dt.y * ah + acy;
    float pw  = expf(dw) * aw;
    float ph  = expf(dh) * ah;
    float x1 = fminf(fmaxf(pcx - 0.5f * pw, 0.0f), W);
    float y1 = fminf(fmaxf(pcy - 0.5f * ph, 0.0f), H);
    float x2 = fminf(fmaxf(pcx + 0.5f * pw, 0.0f), W);
    float y2 = fminf(fmaxf(pcy + 0.5f * ph, 0.0f), H);
    reinterpret_cast<float4*>(g_boxes)[i] = make_float4(x1, y1, x2, y2);
    g_valid[i] = (((x2 - x1) >= MIN_SIZE) && ((y2 - y1) >= MIN_SIZE)) ? 1 : 0;
}

// ---------------------------------------------------------------------------
// K2: single coalesced pass; hot loop = load + 4 compares. Index math, valid
// check and push all live in the rare (1-in-~400) branch.
// ---------------------------------------------------------------------------
#define CA   256     // anchors per block
#define CANT 256

__device__ __forceinline__ void rn_push_g(float s, int bc, unsigned int a) {
    unsigned int pos = atomicAdd(&g_cnt[bc], 1u);
    if (pos < CAPG)
        g_keys[(size_t)bc * CAPG + pos] =
            ((unsigned long long)__float_as_uint(s) << 32) |
            (unsigned long long)(0xFFFFFFFFu - a);
}

__global__ void __launch_bounds__(CANT)
rn_collect(const float* __restrict__ scores, int B, int A, int C) {
    int b   = blockIdx.y;
    int a0  = blockIdx.x * CA;
    int na  = min(CA, A - a0);
    int tid = threadIdx.x;

    if ((C & 3) == 0) {
        unsigned int C4 = (unsigned int)C >> 2;
        const float4* __restrict__ s4 =
            reinterpret_cast<const float4*>(scores + ((size_t)b * A + a0) * C);
        unsigned int n4 = (unsigned int)na * C4;

        #pragma unroll 4
        for (unsigned int i = (unsigned int)tid; i < n4; i += CANT) {
            float4 v = __ldcs(&s4[i]);
            if ((v.x > HLO) | (v.y > HLO) | (v.z > HLO) | (v.w > HLO)) {
                // rare path: recover indices, check validity, push
                unsigned int a  = i / C4;
                unsigned int c4 = (i - a * C4) << 2;
                unsigned int ag = (unsigned int)a0 + a;
                if (g_valid[(size_t)b * A + ag]) {
                    int bc = b * C + (int)c4;
                    if (v.x > HLO) rn_push_g(v.x, bc + 0, ag);
                    if (v.y > HLO) rn_push_g(v.y, bc + 1, ag);
                    if (v.z > HLO) rn_push_g(v.z, bc + 2, ag);
                    if (v.w > HLO) rn_push_g(v.w, bc + 3, ag);
                }
            }
        }
    } else {
        const float* __restrict__ s1 = scores + ((size_t)b * A + a0) * C;
        unsigned int nE = (unsigned int)na * (unsigned int)C;
        for (unsigned int i = (unsigned int)tid; i < nE; i += CANT) {
            float s = s1[i];
            if (s > HLO) {
                unsigned int a = i / (unsigned int)C;
                unsigned int c = i - a * (unsigned int)C;
                unsigned int ag = (unsigned int)a0 + a;
                if (g_valid[(size_t)b * A + ag])
                    rn_push_g(s, b * C + (int)c, ag);
            }
        }
    }
}

// ---------------------------------------------------------------------------
// K3: fused per-class pipeline: threshold + refilter + bitonic sort +
// block-local IoU mask + serial-semantics NMS scan + ranked output.
// ---------------------------------------------------------------------------
__global__ void __launch_bounds__(NTN)
rn_nms(float* __restrict__ out, const float* __restrict__ scores,
       int B, int A, int C) {
    extern __shared__ unsigned char dyn[];
    unsigned int*       ioum = reinterpret_cast<unsigned int*>(dyn);            // [0,32000)
    unsigned int*       fhist = reinterpret_cast<unsigned int*>(dyn);           // alias
    unsigned long long* keys = reinterpret_cast<unsigned long long*>(dyn + 32768);
    float4*             cbox = reinterpret_cast<float4*>(dyn + 49152);          // [512]

    __shared__ float        parea[512];
    __shared__ float        cscore[512];
    __shared__ unsigned int hist64[HBINS];
    __shared__ unsigned int chunk[NTN];
    __shared__ unsigned int keep0[16], keepw[16], pref[16];
    __shared__ unsigned int s_m, s_kk, s_nkeep;
    __shared__ int          s_fb;

    const int tid = threadIdx.x;
    const int bc  = blockIdx.x;
    const int b   = bc / C;
    const int c   = bc % C;

    unsigned int n_raw = g_cnt[bc];
    const unsigned long long* __restrict__ gk = g_keys + (size_t)bc * CAPG;

    if (tid == 0) {
        s_fb = (n_raw < KPRE) || (n_raw > CAPG);
        s_m  = 0;
    }
    if (tid < HBINS) hist64[tid] = 0;
    if (tid < 16) keep0[tid] = 0;
    __syncthreads();

    // ---- fast path: threshold from buffered keys ----
    if (!s_fb) {
        for (unsigned int i = tid; i < n_raw; i += NTN) {
            float s = __uint_as_float((unsigned int)(gk[i] >> 32));
            int bin = min((int)((s - HLO) * HSCALE), HBINS - 1);
            atomicAdd(&hist64[bin], 1u);
        }
        __syncthreads();
        if (tid == 0) {
            unsigned int cum = 0;
            int kk = 0;
            for (int k = HBINS - 1; k >= 0; k--) {
                cum += hist64[k];
                if (cum >= KPRE) { kk = k; break; }
            }
            if (cum > KMAX) s_fb = 1;
            s_kk = (unsigned int)kk;
        }
        __syncthreads();
        if (!s_fb) {
            unsigned int kk = s_kk;
            for (unsigned int i = tid; i < n_raw; i += NTN) {
                unsigned long long key = gk[i];
                float s = __uint_as_float((unsigned int)(key >> 32));
                unsigned int bin =
                    (unsigned int)min((int)((s - HLO) * HSCALE), HBINS - 1);
                if (bin >= kk) {
                    unsigned int pos = atomicAdd(&s_m, 1u);
                    if (pos < KMAX) keys[pos] = key;
                }
            }
        }
        __syncthreads();
    }

    // ---- fallback: exact strided selection (never fires for this data) ----
    if (s_fb) {
        for (int i = tid; i < FBINS; i += NTN) fhist[i] = 0;
        if (tid == 0) s_m = 0;
        __syncthreads();
        for (int a = tid; a < A; a += NTN) {
            float s = scores[((size_t)b * A + a) * (size_t)C + c];
            if (g_valid[(size_t)b * A + a] && s > SCORE_THR) {
                int bin = min(max((int)(s * (float)FBINS), 0), FBINS - 1);
                atomicAdd(&fhist[bin], 1u);
            }
        }
        __syncthreads();
        {
            unsigned int cs = 0;
            const int per = FBINS / NTN;
            #pragma unroll
            for (int i = 0; i < FBINS / NTN; i++) cs += fhist[tid * per + i];
            chunk[tid] = cs;
        }
        __syncthreads();
        if (tid == 0) {
            const int per = FBINS / NTN;
            unsigned int cum = 0;
            int cc;
            for (cc = NTN - 1; cc >= 0; cc--) {
                if (cum + chunk[cc] >= KPRE) break;
                cum += chunk[cc];
            }
            int kk = 0;
            if (cc >= 0) {
                int bs = cc * per;
                for (int bb = bs + per - 1; bb >= bs; bb--) {
                    cum += fhist[bb];
                    if (cum >= KPRE) { kk = bb; break; }
                }
            }
            while (cum > KMAX && kk < FBINS - 1) { cum -= fhist[kk]; kk++; }
            s_kk = (unsigned int)kk;
        }
        __syncthreads();
        unsigned int kk = s_kk;
        __syncthreads();
        for (int a = tid; a < A; a += NTN) {
            float s = scores[((size_t)b * A + a) * (size_t)C + c];
            if (g_valid[(size_t)b * A + a] && s > SCORE_THR) {
                unsigned int bin =
                    (unsigned int)min((int)(s * (float)FBINS), FBINS - 1);
                if (bin >= kk) {
                    unsigned int pos = atomicAdd(&s_m, 1u);
                    if (pos < KMAX)
                        keys[pos] =
                            ((unsigned long long)__float_as_uint(s) << 32) |
                            (unsigned long long)(0xFFFFFFFFu - (unsigned int)a);
                }
            }
        }
        __syncthreads();
    }

    // ---- bitonic sort (1024 or 2048) ----
    unsigned int m = min(s_m, (unsigned int)KMAX);
    const int NSORT = (m <= 1024u) ? 1024 : 2048;
    for (int i = tid; i < NSORT; i += NTN)
        if (i >= (int)m) keys[i] = 0ULL;
    __syncthreads();

    for (int k = 2; k <= NSORT; k <<= 1) {
        for (int j = k >> 1; j > 0; j >>= 1) {
            for (int i = tid; i < NSORT; i += NTN) {
                int ixj = i ^ j;
                if (ixj > i) {
                    unsigned long long x = keys[i];
                    unsigned long long y = keys[ixj];
                    bool desc = ((i & k) == 0);
                    if (desc ? (x < y) : (x > y)) { keys[i] = y; keys[ixj] = x; }
                }
            }
            __syncthreads();
        }
    }

    // ---- candidate setup (reads keys; must finish before ioum aliases it) --
    {
        unsigned long long key = keys[tid];          // tid 0..511
        float s = __uint_as_float((unsigned int)(key >> 32));
        unsigned int aidx = 0xFFFFFFFFu - (unsigned int)(key & 0xFFFFFFFFull);
        bool cv = (tid < KPRE) && (s > SCORE_THR);
        cscore[tid] = s;
        float4 bx = make_float4(0.0f, 0.0f, 0.0f, 0.0f);
        if (cv) bx = reinterpret_cast<const float4*>(g_boxes)[(size_t)b * A + aidx];
        cbox[tid]  = bx;
        parea[tid] = (bx.z - bx.x) * (bx.w - bx.y) * AREA_SCALE;
        if (cv) atomicOr(&keep0[tid >> 5], 1u << (tid & 31));
    }
    __syncthreads();   // keys dead; ioum region reused now

    // ---- IoU mask: 136 upper-triangle (g, ch) jobs, balanced jid%16==warp --
    {
        const int lane = tid & 31;
        const int w    = tid >> 5;
        int jid = 0;
        for (int g = 0; g < 16; g++) {
            for (int ch = g; ch < 16; ch++, jid++) {
                if ((jid & 15) != w) continue;
                int i = g * 32 + lane;
                float4 bi  = cbox[i];
                float  pai = parea[i];
                unsigned int mk = 0;
                int jbase = ch * 32;
                #pragma unroll 8
                for (int jj = 0; jj < 32; jj++) {
                    int j = jbase + jj;              // broadcast LDS
                    float4 bj = cbox[j];
                    float lx = fmaxf(bi.x, bj.x);
                    float ly = fmaxf(bi.y, bj.y);
                    float rx = fminf(bi.z, bj.z);
                    float ry = fminf(bi.w, bj.w);
                    float inter = fmaxf(rx - lx, 0.0f) * fmaxf(ry - ly, 0.0f);
                    bool pred = (inter > pai + parea[j]);
                    if (ch == g) pred = pred && (j > i);
                    mk |= ((unsigned int)pred) << jj;
                }
                if (i < KPRE) ioum[i * 16 + ch] = mk;
            }
        }
    }
    __syncthreads();

    // ---- serial-semantics NMS scan (16 lanes; lower-triangle words unread) -
    if (tid < 16) {
        unsigned int kw = keep0[tid];
        int kept = 0;
        for (int w = 0; w < 16 && kept < MAXDET; w++) {
            unsigned int p = 0;
            while (true) {
                unsigned int cur = __shfl_sync(0xFFFFu, kw, w);
                unsigned int rem = (p < 32u)
                    ? (cur & (p ? (0xFFFFFFFFu << p) : 0xFFFFFFFFu)) : 0u;
                if (!rem) break;
                int bit = __ffs(rem) - 1;
                int i = w * 32 + bit;
                if (tid >= w)                        // only written words
                    kw &= ~ioum[i * 16 + tid];
                kept++;
                if (kept >= MAXDET) break;           // ranks 0..299 final
                p = (unsigned int)bit + 1u;
            }
        }
        keepw[tid] = kw;
        unsigned int pc = __popc(kw);
        unsigned int scan = pc;
        #pragma unroll
        for (int o = 1; o < 16; o <<= 1) {
            unsigned int v = __shfl_up_sync(0xFFFFu, scan, o);
            if (tid >= o) scan += v;
        }
        pref[tid] = scan - pc;
        if (tid == 15) s_nkeep = scan;
    }
    __syncthreads();

    // ---- output ----
    float* outp = out + (size_t)bc * MAXDET * 5;
    if (tid < KPRE) {
        unsigned int kw = keepw[tid >> 5];
        if ((kw >> (tid & 31)) & 1u) {
            unsigned int rank = pref[tid >> 5] + __popc(kw & ((1u << (tid & 31)) - 1u));
            if (rank < MAXDET) {
                float4 bx = cbox[tid];
                outp[rank * 5 + 0] = bx.x;
                outp[rank * 5 + 1] = bx.y;
                outp[rank * 5 + 2] = bx.z;
                outp[rank * 5 + 3] = bx.w;
                outp[rank * 5 + 4] = cscore[tid];
            }
        }
    }
    unsigned int nk = min(s_nkeep, (unsigned int)MAXDET);
    for (int r = (int)nk + tid; r < MAXDET; r += NTN) {
        outp[r * 5 + 0] = 0.0f;
        outp[r * 5 + 1] = 0.0f;
        outp[r * 5 + 2] = 0.0f;
        outp[r * 5 + 3] = 0.0f;
        outp[r * 5 + 4] = -1.0f;
    }
}

// ---------------------------------------------------------------------------
// host launch
// ---------------------------------------------------------------------------
extern "C" void kernel_launch(void* const* d_in, const int* in_sizes, int n_in,
                              void* d_out, int out_size) {
    const float* deltas  = (const float*)d_in[0];
    const float* scores  = (const float*)d_in[1];
    const float* anchors = (const float*)d_in[2];
    const int*   imh     = (const int*)d_in[3];
    const int*   imw     = (const int*)d_in[4];

    long long nd = in_sizes[0];
    long long ns = in_sizes[1];
    int C  = (int)(ns * 4 / nd);
    int BC = out_size / (MAXDET * 5);
    int B  = BC / C;
    int A  = (int)(nd / (4LL * B));

    float* out = (float*)d_out;

    int n = B * A;
    rn_decode<<<(n + 255) / 256, 256>>>(deltas, anchors, imh, imw, B, A);

    dim3 cg((A + CA - 1) / CA, B);
    rn_collect<<<cg, CANT>>>(scores, B, A, C);

    cudaFuncSetAttribute(rn_nms, cudaFuncAttributeMaxDynamicSharedMemorySize, DYN_SMEM);
    rn_nms<<<BC, NTN, DYN_SMEM>>>(out, scores, B, A, C);
}

// round 11
// speedup vs baseline: 1.0949x; 1.0949x over previous
#include <cuda_runtime.h>
#include <stdint.h>

#define KPRE       500
#define MAXDET     300
#define SCORE_THR  0.05f
#define NMS_THR    0.5f
#define MIN_SIZE   0.01f
#define BBOX_CLAMP 4.135166556742356f   // log(1000/16)
#define AREA_SCALE (NMS_THR / (1.0f + NMS_THR))   // thr/(1+thr)

#define HLO        0.99f
#define HBINS      64
#define HSCALE     6400.0f               // HBINS / (1 - HLO)
#define CAPG       16384
#define KMAX       2048
#define FBINS      8192

#define BMAX   2
#define AMAX   131072
#define CMAX   96
#define BCMAX  192

__device__ float              g_boxes[(size_t)BMAX * AMAX * 4];
__device__ unsigned char      g_valid[(size_t)BMAX * AMAX];
__device__ unsigned long long g_keys[(size_t)BCMAX * CAPG];
__device__ unsigned int       g_cnt[BCMAX];
__device__ unsigned long long g_top[(size_t)BCMAX * 512];
__device__ float4             g_cbox[(size_t)BCMAX * 512];
__device__ float              g_parea[(size_t)BCMAX * 512];
__device__ unsigned int       g_ioum[(size_t)BCMAX * KPRE * 16];

// ---------------------------------------------------------------------------
// K1: decode + clamp + valid mask; zero per-class counters
// ---------------------------------------------------------------------------
__global__ void rn_decode(const float* __restrict__ deltas,
                          const float* __restrict__ anchors,
                          const int* __restrict__ imh,
                          const int* __restrict__ imw,
                          int B, int A) {
    int i = blockIdx.x * blockDim.x + threadIdx.x;
    if (i < BCMAX) g_cnt[i] = 0;
    if (i >= B * A) return;
    float W = (float)imw[0];
    float H = (float)imh[0];
    float4 an = reinterpret_cast<const float4*>(anchors)[i];
    float4 dt = reinterpret_cast<const float4*>(deltas)[i];
    float aw  = an.z - an.x;
    float ah  = an.w - an.y;
    float acx = an.x + 0.5f * aw;
    float acy = an.y + 0.5f * ah;
    float dw  = fminf(dt.z, BBOX_CLAMP);
    float dh  = fminf(dt.w, BBOX_CLAMP);
    float pcx = dt.x * aw + acx;
    float pcy = dt.y * ah + acy;
    float pw  = expf(dw) * aw;
    float ph  = expf(dh) * ah;
    float x1 = fminf(fmaxf(pcx - 0.5f * pw, 0.0f), W);
    float y1 = fminf(fmaxf(pcy - 0.5f * ph, 0.0f), H);
    float x2 = fminf(fmaxf(pcx + 0.5f * pw, 0.0f), W);
    float y2 = fminf(fmaxf(pcy + 0.5f * ph, 0.0f), H);
    reinterpret_cast<float4*>(g_boxes)[i] = make_float4(x1, y1, x2, y2);
    g_valid[i] = (((x2 - x1) >= MIN_SIZE) && ((y2 - y1) >= MIN_SIZE)) ? 1 : 0;
}

// ---------------------------------------------------------------------------
// K2: single coalesced pass; explicit 8-deep load batches (MLP=8).
// Hot loop = load + 4 compares; index math / valid / push in rare branch.
// ---------------------------------------------------------------------------
#define CA   256     // anchors per block
#define CANT 256

__device__ __forceinline__ void rn_push_g(float s, int bc, unsigned int a) {
    unsigned int pos = atomicAdd(&g_cnt[bc], 1u);
    if (pos < CAPG)
        g_keys[(size_t)bc * CAPG + pos] =
            ((unsigned long long)__float_as_uint(s) << 32) |
            (unsigned long long)(0xFFFFFFFFu - a);
}

__global__ void __launch_bounds__(CANT)
rn_collect(const float* __restrict__ scores, int B, int A, int C) {
    int b   = blockIdx.y;
    int a0  = blockIdx.x * CA;
    int na  = min(CA, A - a0);
    int tid = threadIdx.x;

    if ((C & 3) == 0) {
        unsigned int C4 = (unsigned int)C >> 2;
        const float4* __restrict__ s4 =
            reinterpret_cast<const float4*>(scores + ((size_t)b * A + a0) * C);
        unsigned int n4 = (unsigned int)na * C4;

        auto proc = [&](float4 v, unsigned int i) {
            if ((v.x > HLO) | (v.y > HLO) | (v.z > HLO) | (v.w > HLO)) {
                unsigned int a  = i / C4;
                unsigned int c4 = (i - a * C4) << 2;
                unsigned int ag = (unsigned int)a0 + a;
                if (g_valid[(size_t)b * A + ag]) {
                    int bc = b * C + (int)c4;
                    if (v.x > HLO) rn_push_g(v.x, bc + 0, ag);
                    if (v.y > HLO) rn_push_g(v.y, bc + 1, ag);
                    if (v.z > HLO) rn_push_g(v.z, bc + 2, ag);
                    if (v.w > HLO) rn_push_g(v.w, bc + 3, ag);
                }
            }
        };

        unsigned int i = (unsigned int)tid;
        for (; i + 7u * CANT < n4; i += 8u * CANT) {
            float4 v[8];
            #pragma unroll
            for (int u = 0; u < 8; u++) v[u] = __ldcs(&s4[i + (unsigned int)u * CANT]);
            #pragma unroll
            for (int u = 0; u < 8; u++) proc(v[u], i + (unsigned int)u * CANT);
        }
        for (; i < n4; i += CANT) proc(__ldcs(&s4[i]), i);
    } else {
        const float* __restrict__ s1 = scores + ((size_t)b * A + a0) * C;
        unsigned int nE = (unsigned int)na * (unsigned int)C;
        for (unsigned int i = (unsigned int)tid; i < nE; i += CANT) {
            float s = s1[i];
            if (s > HLO) {
                unsigned int a = i / (unsigned int)C;
                unsigned int c = i - a * (unsigned int)C;
                unsigned int ag = (unsigned int)a0 + a;
                if (g_valid[(size_t)b * A + ag])
                    rn_push_g(s, b * C + (int)c, ag);
            }
        }
    }
}

// ---------------------------------------------------------------------------
// K3: per-class top-512 by COUNTING RANK (no bitonic): threshold + refilter,
// then rank[i] = #{j : key_j > key_i} via broadcast LDS; scatter to sorted[].
// Epilogue gathers boxes + pre-scaled areas.
// ---------------------------------------------------------------------------
#define SNT 512
#define SORT_SMEM 49152   // [0,32768) fhist (fallback) | [32768,49152) keys[KMAX]

__global__ void __launch_bounds__(SNT)
rn_sort(const float* __restrict__ scores, int B, int A, int C) {
    extern __shared__ unsigned char dyn[];
    unsigned int*       fhist = reinterpret_cast<unsigned int*>(dyn);
    unsigned long long* keys  = reinterpret_cast<unsigned long long*>(dyn + 32768);

    __shared__ unsigned long long sorted[512];
    __shared__ unsigned int hist64[HBINS];
    __shared__ unsigned int chunk[SNT];
    __shared__ unsigned int s_m, s_kk;
    __shared__ int          s_fb;

    const int tid = threadIdx.x;
    const int bc  = blockIdx.x;
    const int b   = bc / C;
    const int c   = bc % C;

    unsigned int n_raw = g_cnt[bc];
    const unsigned long long* __restrict__ gk = g_keys + (size_t)bc * CAPG;

    if (tid == 0) {
        s_fb = (n_raw < KPRE) || (n_raw > CAPG);
        s_m  = 0;
    }
    if (tid < HBINS) hist64[tid] = 0;
    sorted[tid] = 0ULL;
    __syncthreads();

    // ---- fast path: threshold from buffered keys ----
    if (!s_fb) {
        for (unsigned int i = tid; i < n_raw; i += SNT) {
            float s = __uint_as_float((unsigned int)(gk[i] >> 32));
            int bin = min((int)((s - HLO) * HSCALE), HBINS - 1);
            atomicAdd(&hist64[bin], 1u);
        }
        __syncthreads();
        if (tid == 0) {
            unsigned int cum = 0;
            int kk = 0;
            for (int k = HBINS - 1; k >= 0; k--) {
                cum += hist64[k];
                if (cum >= KPRE) { kk = k; break; }
            }
            if (cum > KMAX) s_fb = 1;
            s_kk = (unsigned int)kk;
        }
        __syncthreads();
        if (!s_fb) {
            unsigned int kk = s_kk;
            for (unsigned int i = tid; i < n_raw; i += SNT) {
                unsigned long long key = gk[i];
                float s = __uint_as_float((unsigned int)(key >> 32));
                unsigned int bin =
                    (unsigned int)min((int)((s - HLO) * HSCALE), HBINS - 1);
                if (bin >= kk) {
                    unsigned int pos = atomicAdd(&s_m, 1u);
                    if (pos < KMAX) keys[pos] = key;
                }
            }
        }
        __syncthreads();
    }

    // ---- fallback: exact strided selection (never fires for this data) ----
    if (s_fb) {
        for (int i = tid; i < FBINS; i += SNT) fhist[i] = 0;
        if (tid == 0) s_m = 0;
        __syncthreads();
        for (int a = tid; a < A; a += SNT) {
            float s = scores[((size_t)b * A + a) * (size_t)C + c];
            if (g_valid[(size_t)b * A + a] && s > SCORE_THR) {
                int bin = min(max((int)(s * (float)FBINS), 0), FBINS - 1);
                atomicAdd(&fhist[bin], 1u);
            }
        }
        __syncthreads();
        {
            unsigned int cs = 0;
            const int per = FBINS / SNT;
            #pragma unroll
            for (int i = 0; i < FBINS / SNT; i++) cs += fhist[tid * per + i];
            chunk[tid] = cs;
        }
        __syncthreads();
        if (tid == 0) {
            const int per = FBINS / SNT;
            unsigned int cum = 0;
            int cc;
            for (cc = SNT - 1; cc >= 0; cc--) {
                if (cum + chunk[cc] >= KPRE) break;
                cum += chunk[cc];
            }
            int kk = 0;
            if (cc >= 0) {
                int bs = cc * per;
                for (int bb = bs + per - 1; bb >= bs; bb--) {
                    cum += fhist[bb];
                    if (cum >= KPRE) { kk = bb; break; }
                }
            }
            while (cum > KMAX && kk < FBINS - 1) { cum -= fhist[kk]; kk++; }
            s_kk = (unsigned int)kk;
        }
        __syncthreads();
        unsigned int kk = s_kk;
        __syncthreads();
        for (int a = tid; a < A; a += SNT) {
            float s = scores[((size_t)b * A + a) * (size_t)C + c];
            if (g_valid[(size_t)b * A + a] && s > SCORE_THR) {
                unsigned int bin =
                    (unsigned int)min((int)(s * (float)FBINS), FBINS - 1);
                if (bin >= kk) {
                    unsigned int pos = atomicAdd(&s_m, 1u);
                    if (pos < KMAX)
                        keys[pos] =
                            ((unsigned long long)__float_as_uint(s) << 32) |
                            (unsigned long long)(0xFFFFFFFFu - (unsigned int)a);
                }
            }
        }
        __syncthreads();
    }

    // ---- counting rank (keys are distinct -> ranks are a permutation) ----
    unsigned int m = min(s_m, (unsigned int)KMAX);
    for (unsigned int t = tid; t < m; t += SNT) {
        unsigned long long kt = keys[t];
        unsigned int r = 0;
        unsigned int j = 0;
        #pragma unroll 4
        for (; j + 4 <= m; j += 4) {
            r += (keys[j + 0] > kt);
            r += (keys[j + 1] > kt);
            r += (keys[j + 2] > kt);
            r += (keys[j + 3] > kt);
        }
        for (; j < m; j++) r += (keys[j] > kt);
        if (r < 512u) sorted[r] = kt;
    }
    __syncthreads();

    // ---- epilogue: sorted keys + gathered boxes + pre-scaled areas ----
    {
        unsigned long long key = sorted[tid];
        g_top[(size_t)bc * 512 + tid] = key;
        float s = __uint_as_float((unsigned int)(key >> 32));
        unsigned int aidx = 0xFFFFFFFFu - (unsigned int)(key & 0xFFFFFFFFull);
        float4 bx = make_float4(0.0f, 0.0f, 0.0f, 0.0f);
        if (s > SCORE_THR)
            bx = reinterpret_cast<const float4*>(g_boxes)[(size_t)b * A + aidx];
        g_cbox[(size_t)bc * 512 + tid]  = bx;
        g_parea[(size_t)bc * 512 + tid] =
            (bx.z - bx.x) * (bx.w - bx.y) * AREA_SCALE;
    }
}

// ---------------------------------------------------------------------------
// K4: IoU suppression bitmask. grid (BC, 8) x 256thr; warp = (row-group g,
// quarter q). Condition: inter > pai + paj. Lower triangle never written.
// ---------------------------------------------------------------------------
__global__ void __launch_bounds__(256)
rn_iou(int C) {
    __shared__ float4 cbox[512];
    __shared__ float  parea[512];

    const int tid = threadIdx.x;
    const int bc  = blockIdx.x;

    for (int idx = tid; idx < 512; idx += 256) {
        cbox[idx]  = g_cbox[(size_t)bc * 512 + idx];
        parea[idx] = g_parea[(size_t)bc * 512 + idx];
    }
    __syncthreads();

    const int lane = tid & 31;
    const int widx = blockIdx.y * 8 + (tid >> 5);   // 0..63
    const int g    = widx >> 2;
    const int q    = widx & 3;
    const int i    = g * 32 + lane;
    const bool vi  = (i < KPRE);

    float4 bi  = cbox[i];
    float  pai = parea[i];

    unsigned int* __restrict__ om = g_ioum + (size_t)bc * KPRE * 16;

    int ch0 = g + ((q - g) & 3);
    for (int ch = ch0; ch < 16; ch += 4) {
        unsigned int m = 0;
        int jbase = ch * 32;
        if (ch == g) {
            #pragma unroll 8
            for (int jj = 0; jj < 32; jj++) {
                int j = jbase + jj;
                float4 bj = cbox[j];
                float lx = fmaxf(bi.x, bj.x);
                float ly = fmaxf(bi.y, bj.y);
                float rx = fminf(bi.z, bj.z);
                float ry = fminf(bi.w, bj.w);
                float inter = fmaxf(rx - lx, 0.0f) * fmaxf(ry - ly, 0.0f);
                bool pred = (j > i) && (inter > pai + parea[j]);
                m |= ((unsigned int)pred) << jj;
            }
        } else {
            #pragma unroll 8
            for (int jj = 0; jj < 32; jj++) {
                int j = jbase + jj;
                float4 bj = cbox[j];
                float lx = fmaxf(bi.x, bj.x);
                float ly = fmaxf(bi.y, bj.y);
                float rx = fminf(bi.z, bj.z);
                float ry = fminf(bi.w, bj.w);
                float inter = fmaxf(rx - lx, 0.0f) * fmaxf(ry - ly, 0.0f);
                bool pred = (inter > pai + parea[j]);
                m |= ((unsigned int)pred) << jj;
            }
        }
        if (vi) om[i * 16 + ch] = m;
    }
}

// ---------------------------------------------------------------------------
// K5: serial-semantics NMS scan (single-lane, register-resident keep words)
// + ranked output. Lower-triangle mask words unwritten -> only k>=w applied.
// ---------------------------------------------------------------------------
__global__ void __launch_bounds__(512)
rn_scan(float* __restrict__ out, int B, int A, int C) {
    __shared__ unsigned int ioum[KPRE * 16];   // 32000 B
    __shared__ float4       cbox[KPRE];        // 8000 B
    __shared__ float        cscore[KPRE];
    __shared__ unsigned int keep0[16], keepw[16], pref[16];
    __shared__ unsigned int s_nkeep;

    const int tid = threadIdx.x;
    const int bc  = blockIdx.x;

    if (tid < 16) keep0[tid] = 0;
    {
        const uint4* __restrict__ src =
            reinterpret_cast<const uint4*>(g_ioum + (size_t)bc * KPRE * 16);
        uint4* dst = reinterpret_cast<uint4*>(ioum);
        for (int i = tid; i < KPRE * 4; i += 512) dst[i] = src[i];
    }
    if (tid < KPRE) {
        unsigned long long key = g_top[(size_t)bc * 512 + tid];
        float s = __uint_as_float((unsigned int)(key >> 32));
        bool cv = (s > SCORE_THR);
        cscore[tid] = s;
        cbox[tid]   = g_cbox[(size_t)bc * 512 + tid];
        if (cv) atomicOr(&keep0[tid >> 5], 1u << (tid & 31));
    }
    __syncthreads();

    if (tid == 0) {
        unsigned int kw[16];
        #pragma unroll
        for (int w = 0; w < 16; w++) kw[w] = keep0[w];
        int kept = 0;
        #pragma unroll
        for (int w = 0; w < 16; w++) {
            if (kept >= MAXDET) break;
            unsigned int p = 0;
            while (p < 32u && kept < MAXDET) {
                unsigned int rem = kw[w] & (0xFFFFFFFFu << p);
                if (!rem) break;
                int bit = __ffs(rem) - 1;
                int i = w * 32 + bit;
                // apply row i's suppression to words >= w (others unwritten)
                #pragma unroll
                for (int k = 0; k < 16; k++)
                    if (k >= w) kw[k] &= ~ioum[i * 16 + k];
                kept++;
                p = (unsigned int)bit + 1u;
            }
        }
        unsigned int acc = 0;
        #pragma unroll
        for (int w = 0; w < 16; w++) {
            keepw[w] = kw[w];
            pref[w]  = acc;
            acc += __popc(kw[w]);
        }
        s_nkeep = acc;
    }
    __syncthreads();

    float* outp = out + (size_t)bc * MAXDET * 5;
    if (tid < KPRE) {
        unsigned int kw = keepw[tid >> 5];
        if ((kw >> (tid & 31)) & 1u) {
            unsigned int rank = pref[tid >> 5] + __popc(kw & ((1u << (tid & 31)) - 1u));
            if (rank < MAXDET) {
                float4 bx = cbox[tid];
                outp[rank * 5 + 0] = bx.x;
                outp[rank * 5 + 1] = bx.y;
                outp[rank * 5 + 2] = bx.z;
                outp[rank * 5 + 3] = bx.w;
                outp[rank * 5 + 4] = cscore[tid];
            }
        }
    }
    unsigned int nk = min(s_nkeep, (unsigned int)MAXDET);
    for (int r = (int)nk + tid; r < MAXDET; r += 512) {
        outp[r * 5 + 0] = 0.0f;
        outp[r * 5 + 1] = 0.0f;
        outp[r * 5 + 2] = 0.0f;
        outp[r * 5 + 3] = 0.0f;
        outp[r * 5 + 4] = -1.0f;
    }
}

// ---------------------------------------------------------------------------
// host launch
// ---------------------------------------------------------------------------
extern "C" void kernel_launch(void* const* d_in, const int* in_sizes, int n_in,
                              void* d_out, int out_size) {
    const float* deltas  = (const float*)d_in[0];
    const float* scores  = (const float*)d_in[1];
    const float* anchors = (const float*)d_in[2];
    const int*   imh     = (const int*)d_in[3];
    const int*   imw     = (const int*)d_in[4];

    long long nd = in_sizes[0];
    long long ns = in_sizes[1];
    int C  = (int)(ns * 4 / nd);
    int BC = out_size / (MAXDET * 5);
    int B  = BC / C;
    int A  = (int)(nd / (4LL * B));

    float* out = (float*)d_out;

    int n = B * A;
    rn_decode<<<(n + 255) / 256, 256>>>(deltas, anchors, imh, imw, B, A);

    dim3 cg((A + CA - 1) / CA, B);
    rn_collect<<<cg, CANT>>>(scores, B, A, C);

    cudaFuncSetAttribute(rn_sort, cudaFuncAttributeMaxDynamicSharedMemorySize, SORT_SMEM);
    rn_sort<<<BC, SNT, SORT_SMEM>>>(scores, B, A, C);
    rn_iou<<<dim3(BC, 8), 256>>>(C);
    rn_scan<<<BC, 512>>>(out, B, A, C);
}

// round 12
// speedup vs baseline: 1.1078x; 1.0118x over previous
#include <cuda_runtime.h>
#include <stdint.h>

#define KPRE       500
#define MAXDET     300
#define SCORE_THR  0.05f
#define NMS_THR    0.5f
#define MIN_SIZE   0.01f
#define BBOX_CLAMP 4.135166556742356f   // log(1000/16)
#define AREA_SCALE (NMS_THR / (1.0f + NMS_THR))   // thr/(1+thr)

#define HLO        0.99f
#define HBINS      64
#define HSCALE     6400.0f               // HBINS / (1 - HLO)
#define CAPG       16384
#define KMAX       2048
#define FBINS      8192

#define BMAX   2
#define AMAX   131072
#define CMAX   96
#define BCMAX  192

__device__ float              g_boxes[(size_t)BMAX * AMAX * 4];
__device__ unsigned char      g_valid[(size_t)BMAX * AMAX];
__device__ unsigned long long g_keys[(size_t)BCMAX * CAPG];
__device__ unsigned int       g_cnt[BCMAX];
__device__ unsigned long long g_top[(size_t)BCMAX * 512];
__device__ float4             g_cbox[(size_t)BCMAX * 512];
__device__ float              g_parea[(size_t)BCMAX * 512];
__device__ unsigned int       g_ioum[(size_t)BCMAX * KPRE * 16];

// ---------------------------------------------------------------------------
// K1: decode + clamp + valid mask; zero per-class counters
// ---------------------------------------------------------------------------
__global__ void rn_decode(const float* __restrict__ deltas,
                          const float* __restrict__ anchors,
                          const int* __restrict__ imh,
                          const int* __restrict__ imw,
                          int B, int A) {
    int i = blockIdx.x * blockDim.x + threadIdx.x;
    if (i < BCMAX) g_cnt[i] = 0;
    if (i >= B * A) return;
    float W = (float)imw[0];
    float H = (float)imh[0];
    float4 an = reinterpret_cast<const float4*>(anchors)[i];
    float4 dt = reinterpret_cast<const float4*>(deltas)[i];
    float aw  = an.z - an.x;
    float ah  = an.w - an.y;
    float acx = an.x + 0.5f * aw;
    float acy = an.y + 0.5f * ah;
    float dw  = fminf(dt.z, BBOX_CLAMP);
    float dh  = fminf(dt.w, BBOX_CLAMP);
    float pcx = dt.x * aw + acx;
    float pcy = dt.y * ah + acy;
    float pw  = expf(dw) * aw;
    float ph  = expf(dh) * ah;
    float x1 = fminf(fmaxf(pcx - 0.5f * pw, 0.0f), W);
    float y1 = fminf(fmaxf(pcy - 0.5f * ph, 0.0f), H);
    float x2 = fminf(fmaxf(pcx + 0.5f * pw, 0.0f), W);
    float y2 = fminf(fmaxf(pcy + 0.5f * ph, 0.0f), H);
    reinterpret_cast<float4*>(g_boxes)[i] = make_float4(x1, y1, x2, y2);
    g_valid[i] = (((x2 - x1) >= MIN_SIZE) && ((y2 - y1) >= MIN_SIZE)) ? 1 : 0;
}

// ---------------------------------------------------------------------------
// K2: single coalesced pass. Detection via fmax-tree (1 FMNMX per value,
// 1 FSETP per 8 values); exact re-check + push only in the rare branch.
// ---------------------------------------------------------------------------
#define CA   256     // anchors per block
#define CANT 256

__device__ __forceinline__ void rn_push_g(float s, int bc, unsigned int a) {
    unsigned int pos = atomicAdd(&g_cnt[bc], 1u);
    if (pos < CAPG)
        g_keys[(size_t)bc * CAPG + pos] =
            ((unsigned long long)__float_as_uint(s) << 32) |
            (unsigned long long)(0xFFFFFFFFu - a);
}

__global__ void __launch_bounds__(CANT)
rn_collect(const float* __restrict__ scores, int B, int A, int C) {
    int b   = blockIdx.y;
    int a0  = blockIdx.x * CA;
    int na  = min(CA, A - a0);
    int tid = threadIdx.x;

    if ((C & 3) == 0) {
        unsigned int C4 = (unsigned int)C >> 2;
        const float4* __restrict__ s4 =
            reinterpret_cast<const float4*>(scores + ((size_t)b * A + a0) * C);
        unsigned int n4 = (unsigned int)na * C4;

        // exact per-float4 handling (rare path)
        auto proc = [&](float4 v, unsigned int i) {
            unsigned int a  = i / C4;
            unsigned int c4 = (i - a * C4) << 2;
            unsigned int ag = (unsigned int)a0 + a;
            if (g_valid[(size_t)b * A + ag]) {
                int bc = b * C + (int)c4;
                if (v.x > HLO) rn_push_g(v.x, bc + 0, ag);
                if (v.y > HLO) rn_push_g(v.y, bc + 1, ag);
                if (v.z > HLO) rn_push_g(v.z, bc + 2, ag);
                if (v.w > HLO) rn_push_g(v.w, bc + 3, ag);
            }
        };

        unsigned int i = (unsigned int)tid;
        for (; i + 7u * CANT < n4; i += 8u * CANT) {
            float4 v[8];
            #pragma unroll
            for (int u = 0; u < 8; u++)
                v[u] = __ldcs(&s4[i + (unsigned int)u * CANT]);
            #pragma unroll
            for (int p = 0; p < 4; p++) {
                float4 va = v[2 * p];
                float4 vb = v[2 * p + 1];
                // 7-op max tree over 8 values
                float m0 = fmaxf(va.x, va.y);
                float m1 = fmaxf(va.z, va.w);
                float m2 = fmaxf(vb.x, vb.y);
                float m3 = fmaxf(vb.z, vb.w);
                float m4 = fmaxf(m0, m1);
                float m5 = fmaxf(m2, m3);
                float mm = fmaxf(m4, m5);
                if (mm > HLO) {
                    unsigned int ia = i + (unsigned int)(2 * p) * CANT;
                    unsigned int ib = ia + CANT;
                    if (fmaxf(m4, -1.0f) > HLO) proc(va, ia);   // va side
                    if (m5 > HLO)               proc(vb, ib);   // vb side
                }
            }
        }
        for (; i < n4; i += CANT) {
            float4 va = __ldcs(&s4[i]);
            float mm = fmaxf(fmaxf(va.x, va.y), fmaxf(va.z, va.w));
            if (mm > HLO) proc(va, i);
        }
    } else {
        const float* __restrict__ s1 = scores + ((size_t)b * A + a0) * C;
        unsigned int nE = (unsigned int)na * (unsigned int)C;
        for (unsigned int i = (unsigned int)tid; i < nE; i += CANT) {
            float s = s1[i];
            if (s > HLO) {
                unsigned int a = i / (unsigned int)C;
                unsigned int c = i - a * (unsigned int)C;
                unsigned int ag = (unsigned int)a0 + a;
                if (g_valid[(size_t)b * A + ag])
                    rn_push_g(s, b * C + (int)c, ag);
            }
        }
    }
}

// ---------------------------------------------------------------------------
// K3: per-class top-512 by counting rank; epilogue gathers boxes + areas
// ---------------------------------------------------------------------------
#define SNT 512
#define SORT_SMEM 49152   // [0,32768) fhist (fallback) | [32768,49152) keys[KMAX]

__global__ void __launch_bounds__(SNT)
rn_sort(const float* __restrict__ scores, int B, int A, int C) {
    extern __shared__ unsigned char dyn[];
    unsigned int*       fhist = reinterpret_cast<unsigned int*>(dyn);
    unsigned long long* keys  = reinterpret_cast<unsigned long long*>(dyn + 32768);

    __shared__ unsigned long long sorted[512];
    __shared__ unsigned int hist64[HBINS];
    __shared__ unsigned int chunk[SNT];
    __shared__ unsigned int s_m, s_kk;
    __shared__ int          s_fb;

    const int tid = threadIdx.x;
    const int bc  = blockIdx.x;
    const int b   = bc / C;
    const int c   = bc % C;

    unsigned int n_raw = g_cnt[bc];
    const unsigned long long* __restrict__ gk = g_keys + (size_t)bc * CAPG;

    if (tid == 0) {
        s_fb = (n_raw < KPRE) || (n_raw > CAPG);
        s_m  = 0;
    }
    if (tid < HBINS) hist64[tid] = 0;
    sorted[tid] = 0ULL;
    __syncthreads();

    if (!s_fb) {
        for (unsigned int i = tid; i < n_raw; i += SNT) {
            float s = __uint_as_float((unsigned int)(gk[i] >> 32));
            int bin = min((int)((s - HLO) * HSCALE), HBINS - 1);
            atomicAdd(&hist64[bin], 1u);
        }
        __syncthreads();
        if (tid == 0) {
            unsigned int cum = 0;
            int kk = 0;
            for (int k = HBINS - 1; k >= 0; k--) {
                cum += hist64[k];
                if (cum >= KPRE) { kk = k; break; }
            }
            if (cum > KMAX) s_fb = 1;
            s_kk = (unsigned int)kk;
        }
        __syncthreads();
        if (!s_fb) {
            unsigned int kk = s_kk;
            for (unsigned int i = tid; i < n_raw; i += SNT) {
                unsigned long long key = gk[i];
                float s = __uint_as_float((unsigned int)(key >> 32));
                unsigned int bin =
                    (unsigned int)min((int)((s - HLO) * HSCALE), HBINS - 1);
                if (bin >= kk) {
                    unsigned int pos = atomicAdd(&s_m, 1u);
                    if (pos < KMAX) keys[pos] = key;
                }
            }
        }
        __syncthreads();
    }

    if (s_fb) {   // exact strided fallback
        for (int i = tid; i < FBINS; i += SNT) fhist[i] = 0;
        if (tid == 0) s_m = 0;
        __syncthreads();
        for (int a = tid; a < A; a += SNT) {
            float s = scores[((size_t)b * A + a) * (size_t)C + c];
            if (g_valid[(size_t)b * A + a] && s > SCORE_THR) {
                int bin = min(max((int)(s * (float)FBINS), 0), FBINS - 1);
                atomicAdd(&fhist[bin], 1u);
            }
        }
        __syncthreads();
        {
            unsigned int cs = 0;
            const int per = FBINS / SNT;
            #pragma unroll
            for (int i = 0; i < FBINS / SNT; i++) cs += fhist[tid * per + i];
            chunk[tid] = cs;
        }
        __syncthreads();
        if (tid == 0) {
            const int per = FBINS / SNT;
            unsigned int cum = 0;
            int cc;
            for (cc = SNT - 1; cc >= 0; cc--) {
                if (cum + chunk[cc] >= KPRE) break;
                cum += chunk[cc];
            }
            int kk = 0;
            if (cc >= 0) {
                int bs = cc * per;
                for (int bb = bs + per - 1; bb >= bs; bb--) {
                    cum += fhist[bb];
                    if (cum >= KPRE) { kk = bb; break; }
                }
            }
            while (cum > KMAX && kk < FBINS - 1) { cum -= fhist[kk]; kk++; }
            s_kk = (unsigned int)kk;
        }
        __syncthreads();
        unsigned int kk = s_kk;
        __syncthreads();
        for (int a = tid; a < A; a += SNT) {
            float s = scores[((size_t)b * A + a) * (size_t)C + c];
            if (g_valid[(size_t)b * A + a] && s > SCORE_THR) {
                unsigned int bin =
                    (unsigned int)min((int)(s * (float)FBINS), FBINS - 1);
                if (bin >= kk) {
                    unsigned int pos = atomicAdd(&s_m, 1u);
                    if (pos < KMAX)
                        keys[pos] =
                            ((unsigned long long)__float_as_uint(s) << 32) |
                            (unsigned long long)(0xFFFFFFFFu - (unsigned int)a);
                }
            }
        }
        __syncthreads();
    }

    // counting rank (keys distinct -> permutation)
    unsigned int m = min(s_m, (unsigned int)KMAX);
    for (unsigned int t = tid; t < m; t += SNT) {
        unsigned long long kt = keys[t];
        unsigned int r = 0;
        unsigned int j = 0;
        #pragma unroll 4
        for (; j + 4 <= m; j += 4) {
            r += (keys[j + 0] > kt);
            r += (keys[j + 1] > kt);
            r += (keys[j + 2] > kt);
            r += (keys[j + 3] > kt);
        }
        for (; j < m; j++) r += (keys[j] > kt);
        if (r < 512u) sorted[r] = kt;
    }
    __syncthreads();

    {
        unsigned long long key = sorted[tid];
        g_top[(size_t)bc * 512 + tid] = key;
        float s = __uint_as_float((unsigned int)(key >> 32));
        unsigned int aidx = 0xFFFFFFFFu - (unsigned int)(key & 0xFFFFFFFFull);
        float4 bx = make_float4(0.0f, 0.0f, 0.0f, 0.0f);
        if (s > SCORE_THR)
            bx = reinterpret_cast<const float4*>(g_boxes)[(size_t)b * A + aidx];
        g_cbox[(size_t)bc * 512 + tid]  = bx;
        g_parea[(size_t)bc * 512 + tid] =
            (bx.z - bx.x) * (bx.w - bx.y) * AREA_SCALE;
    }
}

// ---------------------------------------------------------------------------
// K4: IoU suppression bitmask. grid (BC, 8) x 256thr.
// ---------------------------------------------------------------------------
__global__ void __launch_bounds__(256)
rn_iou(int C) {
    __shared__ float4 cbox[512];
    __shared__ float  parea[512];

    const int tid = threadIdx.x;
    const int bc  = blockIdx.x;

    for (int idx = tid; idx < 512; idx += 256) {
        cbox[idx]  = g_cbox[(size_t)bc * 512 + idx];
        parea[idx] = g_parea[(size_t)bc * 512 + idx];
    }
    __syncthreads();

    const int lane = tid & 31;
    const int widx = blockIdx.y * 8 + (tid >> 5);
    const int g    = widx >> 2;
    const int q    = widx & 3;
    const int i    = g * 32 + lane;
    const bool vi  = (i < KPRE);

    float4 bi  = cbox[i];
    float  pai = parea[i];

    unsigned int* __restrict__ om = g_ioum + (size_t)bc * KPRE * 16;

    int ch0 = g + ((q - g) & 3);
    for (int ch = ch0; ch < 16; ch += 4) {
        unsigned int m = 0;
        int jbase = ch * 32;
        if (ch == g) {
            #pragma unroll 8
            for (int jj = 0; jj < 32; jj++) {
                int j = jbase + jj;
                float4 bj = cbox[j];
                float lx = fmaxf(bi.x, bj.x);
                float ly = fmaxf(bi.y, bj.y);
                float rx = fminf(bi.z, bj.z);
                float ry = fminf(bi.w, bj.w);
                float inter = fmaxf(rx - lx, 0.0f) * fmaxf(ry - ly, 0.0f);
                bool pred = (j > i) && (inter > pai + parea[j]);
                m |= ((unsigned int)pred) << jj;
            }
        } else {
            #pragma unroll 8
            for (int jj = 0; jj < 32; jj++) {
                int j = jbase + jj;
                float4 bj = cbox[j];
                float lx = fmaxf(bi.x, bj.x);
                float ly = fmaxf(bi.y, bj.y);
                float rx = fminf(bi.z, bj.z);
                float ry = fminf(bi.w, bj.w);
                float inter = fmaxf(rx - lx, 0.0f) * fmaxf(ry - ly, 0.0f);
                bool pred = (inter > pai + parea[j]);
                m |= ((unsigned int)pred) << jj;
            }
        }
        if (vi) om[i * 16 + ch] = m;
    }
}

// ---------------------------------------------------------------------------
// K5: serial-semantics NMS scan (single-lane, register keep words) + output
// ---------------------------------------------------------------------------
__global__ void __launch_bounds__(512)
rn_scan(float* __restrict__ out, int B, int A, int C) {
    __shared__ unsigned int ioum[KPRE * 16];
    __shared__ float4       cbox[KPRE];
    __shared__ float        cscore[KPRE];
    __shared__ unsigned int keep0[16], keepw[16], pref[16];
    __shared__ unsigned int s_nkeep;

    const int tid = threadIdx.x;
    const int bc  = blockIdx.x;

    if (tid < 16) keep0[tid] = 0;
    {
        const uint4* __restrict__ src =
            reinterpret_cast<const uint4*>(g_ioum + (size_t)bc * KPRE * 16);
        uint4* dst = reinterpret_cast<uint4*>(ioum);
        for (int i = tid; i < KPRE * 4; i += 512) dst[i] = src[i];
    }
    if (tid < KPRE) {
        unsigned long long key = g_top[(size_t)bc * 512 + tid];
        float s = __uint_as_float((unsigned int)(key >> 32));
        bool cv = (s > SCORE_THR);
        cscore[tid] = s;
        cbox[tid]   = g_cbox[(size_t)bc * 512 + tid];
        if (cv) atomicOr(&keep0[tid >> 5], 1u << (tid & 31));
    }
    __syncthreads();

    if (tid == 0) {
        unsigned int kw[16];
        #pragma unroll
        for (int w = 0; w < 16; w++) kw[w] = keep0[w];
        int kept = 0;
        #pragma unroll
        for (int w = 0; w < 16; w++) {
            if (kept >= MAXDET) break;
            unsigned int p = 0;
            while (p < 32u && kept < MAXDET) {
                unsigned int rem = kw[w] & (0xFFFFFFFFu << p);
                if (!rem) break;
                int bit = __ffs(rem) - 1;
                int i = w * 32 + bit;
                #pragma unroll
                for (int k = 0; k < 16; k++)
                    if (k >= w) kw[k] &= ~ioum[i * 16 + k];
                kept++;
                p = (unsigned int)bit + 1u;
            }
        }
        unsigned int acc = 0;
        #pragma unroll
        for (int w = 0; w < 16; w++) {
            keepw[w] = kw[w];
            pref[w]  = acc;
            acc += __popc(kw[w]);
        }
        s_nkeep = acc;
    }
    __syncthreads();

    float* outp = out + (size_t)bc * MAXDET * 5;
    if (tid < KPRE) {
        unsigned int kw = keepw[tid >> 5];
        if ((kw >> (tid & 31)) & 1u) {
            unsigned int rank = pref[tid >> 5] + __popc(kw & ((1u << (tid & 31)) - 1u));
            if (rank < MAXDET) {
                float4 bx = cbox[tid];
                outp[rank * 5 + 0] = bx.x;
                outp[rank * 5 + 1] = bx.y;
                outp[rank * 5 + 2] = bx.z;
                outp[rank * 5 + 3] = bx.w;
                outp[rank * 5 + 4] = cscore[tid];
            }
        }
    }
    unsigned int nk = min(s_nkeep, (unsigned int)MAXDET);
    for (int r = (int)nk + tid; r < MAXDET; r += 512) {
        outp[r * 5 + 0] = 0.0f;
        outp[r * 5 + 1] = 0.0f;
        outp[r * 5 + 2] = 0.0f;
        outp[r * 5 + 3] = 0.0f;
        outp[r * 5 + 4] = -1.0f;
    }
}

// ---------------------------------------------------------------------------
// host launch
// ---------------------------------------------------------------------------
extern "C" void kernel_launch(void* const* d_in, const int* in_sizes, int n_in,
                              void* d_out, int out_size) {
    const float* deltas  = (const float*)d_in[0];
    const float* scores  = (const float*)d_in[1];
    const float* anchors = (const float*)d_in[2];
    const int*   imh     = (const int*)d_in[3];
    const int*   imw     = (const int*)d_in[4];

    long long nd = in_sizes[0];
    long long ns = in_sizes[1];
    int C  = (int)(ns * 4 / nd);
    int BC = out_size / (MAXDET * 5);
    int B  = BC / C;
    int A  = (int)(nd / (4LL * B));

    float* out = (float*)d_out;

    int n = B * A;
    rn_decode<<<(n + 255) / 256, 256>>>(deltas, anchors, imh, imw, B, A);

    dim3 cg((A + CA - 1) / CA, B);
    rn_collect<<<cg, CANT>>>(scores, B, A, C);

    cudaFuncSetAttribute(rn_sort, cudaFuncAttributeMaxDynamicSharedMemorySize, SORT_SMEM);
    rn_sort<<<BC, SNT, SORT_SMEM>>>(scores, B, A, C);
    rn_iou<<<dim3(BC, 8), 256>>>(C);
    rn_scan<<<BC, 512>>>(out, B, A, C);
}

// round 13
// speedup vs baseline: 1.1246x; 1.0151x over previous
#include <cuda_runtime.h>
#include <stdint.h>

#define KPRE       500
#define MAXDET     300
#define SCORE_THR  0.05f
#define NMS_THR    0.5f
#define MIN_SIZE   0.01f
#define BBOX_CLAMP 4.135166556742356f   // log(1000/16)
#define AREA_SCALE (NMS_THR / (1.0f + NMS_THR))   // thr/(1+thr)

#define HLO        0.99f
#define HBINS      64
#define HSCALE     6400.0f               // HBINS / (1 - HLO)
#define CAPG       16384
#define KMAX       2048
#define FBINS      8192

#define BMAX   2
#define AMAX   131072
#define CMAX   96
#define BCMAX  192

__device__ float              g_boxes[(size_t)BMAX * AMAX * 4];
__device__ unsigned char      g_valid[(size_t)BMAX * AMAX];
__device__ unsigned long long g_keys[(size_t)BCMAX * CAPG];
__device__ unsigned int       g_cnt[BCMAX];
__device__ unsigned long long g_top[(size_t)BCMAX * 512];
__device__ float4             g_cbox[(size_t)BCMAX * 512];
__device__ float              g_parea[(size_t)BCMAX * 512];
__device__ unsigned int       g_ioum[(size_t)BCMAX * KPRE * 16];

// ---------------------------------------------------------------------------
// K1: decode + clamp + valid mask; zero per-class counters
// ---------------------------------------------------------------------------
__global__ void rn_decode(const float* __restrict__ deltas,
                          const float* __restrict__ anchors,
                          const int* __restrict__ imh,
                          const int* __restrict__ imw,
                          int B, int A) {
    int i = blockIdx.x * blockDim.x + threadIdx.x;
    if (i < BCMAX) g_cnt[i] = 0;
    if (i >= B * A) return;
    float W = (float)imw[0];
    float H = (float)imh[0];
    float4 an = reinterpret_cast<const float4*>(anchors)[i];
    float4 dt = reinterpret_cast<const float4*>(deltas)[i];
    float aw  = an.z - an.x;
    float ah  = an.w - an.y;
    float acx = an.x + 0.5f * aw;
    float acy = an.y + 0.5f * ah;
    float dw  = fminf(dt.z, BBOX_CLAMP);
    float dh  = fminf(dt.w, BBOX_CLAMP);
    float pcx = dt.x * aw + acx;
    float pcy = dt.y * ah + acy;
    float pw  = expf(dw) * aw;
    float ph  = expf(dh) * ah;
    float x1 = fminf(fmaxf(pcx - 0.5f * pw, 0.0f), W);
    float y1 = fminf(fmaxf(pcy - 0.5f * ph, 0.0f), H);
    float x2 = fminf(fmaxf(pcx + 0.5f * pw, 0.0f), W);
    float y2 = fminf(fmaxf(pcy + 0.5f * ph, 0.0f), H);
    reinterpret_cast<float4*>(g_boxes)[i] = make_float4(x1, y1, x2, y2);
    g_valid[i] = (((x2 - x1) >= MIN_SIZE) && ((y2 - y1) >= MIN_SIZE)) ? 1 : 0;
}

// ---------------------------------------------------------------------------
// K2: single coalesced pass. fmax-tree detection; exact re-check in rare
// branch. CA=128 -> 2x concurrent CTAs vs R12; plain LDG (no __ldcs).
// ---------------------------------------------------------------------------
#define CA   128     // anchors per block
#define CANT 256

__device__ __forceinline__ void rn_push_g(float s, int bc, unsigned int a) {
    unsigned int pos = atomicAdd(&g_cnt[bc], 1u);
    if (pos < CAPG)
        g_keys[(size_t)bc * CAPG + pos] =
            ((unsigned long long)__float_as_uint(s) << 32) |
            (unsigned long long)(0xFFFFFFFFu - a);
}

__global__ void __launch_bounds__(CANT)
rn_collect(const float* __restrict__ scores, int B, int A, int C) {
    int b   = blockIdx.y;
    int a0  = blockIdx.x * CA;
    int na  = min(CA, A - a0);
    int tid = threadIdx.x;

    if ((C & 3) == 0) {
        unsigned int C4 = (unsigned int)C >> 2;
        const float4* __restrict__ s4 =
            reinterpret_cast<const float4*>(scores + ((size_t)b * A + a0) * C);
        unsigned int n4 = (unsigned int)na * C4;

        auto proc = [&](float4 v, unsigned int i) {
            unsigned int a  = i / C4;
            unsigned int c4 = (i - a * C4) << 2;
            unsigned int ag = (unsigned int)a0 + a;
            if (g_valid[(size_t)b * A + ag]) {
                int bc = b * C + (int)c4;
                if (v.x > HLO) rn_push_g(v.x, bc + 0, ag);
                if (v.y > HLO) rn_push_g(v.y, bc + 1, ag);
                if (v.z > HLO) rn_push_g(v.z, bc + 2, ag);
                if (v.w > HLO) rn_push_g(v.w, bc + 3, ag);
            }
        };

        unsigned int i = (unsigned int)tid;
        for (; i + 7u * CANT < n4; i += 8u * CANT) {
            float4 v[8];
            #pragma unroll
            for (int u = 0; u < 8; u++)
                v[u] = s4[i + (unsigned int)u * CANT];
            #pragma unroll
            for (int p = 0; p < 4; p++) {
                float4 va = v[2 * p];
                float4 vb = v[2 * p + 1];
                float m0 = fmaxf(va.x, va.y);
                float m1 = fmaxf(va.z, va.w);
                float m2 = fmaxf(vb.x, vb.y);
                float m3 = fmaxf(vb.z, vb.w);
                float m4 = fmaxf(m0, m1);
                float m5 = fmaxf(m2, m3);
                float mm = fmaxf(m4, m5);
                if (mm > HLO) {
                    unsigned int ia = i + (unsigned int)(2 * p) * CANT;
                    unsigned int ib = ia + CANT;
                    if (m4 > HLO) proc(va, ia);
                    if (m5 > HLO) proc(vb, ib);
                }
            }
        }
        for (; i < n4; i += CANT) {
            float4 va = s4[i];
            float mm = fmaxf(fmaxf(va.x, va.y), fmaxf(va.z, va.w));
            if (mm > HLO) proc(va, i);
        }
    } else {
        const float* __restrict__ s1 = scores + ((size_t)b * A + a0) * C;
        unsigned int nE = (unsigned int)na * (unsigned int)C;
        for (unsigned int i = (unsigned int)tid; i < nE; i += CANT) {
            float s = s1[i];
            if (s > HLO) {
                unsigned int a = i / (unsigned int)C;
                unsigned int c = i - a * (unsigned int)C;
                unsigned int ag = (unsigned int)a0 + a;
                if (g_valid[(size_t)b * A + ag])
                    rn_push_g(s, b * C + (int)c, ag);
            }
        }
    }
}

// ---------------------------------------------------------------------------
// K3: per-class top-512 by counting rank; epilogue gathers boxes + areas
// ---------------------------------------------------------------------------
#define SNT 512
#define SORT_SMEM 49152   // [0,32768) fhist (fallback) | [32768,49152) keys[KMAX]

__global__ void __launch_bounds__(SNT)
rn_sort(const float* __restrict__ scores, int B, int A, int C) {
    extern __shared__ unsigned char dyn[];
    unsigned int*       fhist = reinterpret_cast<unsigned int*>(dyn);
    unsigned long long* keys  = reinterpret_cast<unsigned long long*>(dyn + 32768);

    __shared__ unsigned long long sorted[512];
    __shared__ unsigned int hist64[HBINS];
    __shared__ unsigned int chunk[SNT];
    __shared__ unsigned int s_m, s_kk;
    __shared__ int          s_fb;

    const int tid = threadIdx.x;
    const int bc  = blockIdx.x;
    const int b   = bc / C;
    const int c   = bc % C;

    unsigned int n_raw = g_cnt[bc];
    const unsigned long long* __restrict__ gk = g_keys + (size_t)bc * CAPG;

    if (tid == 0) {
        s_fb = (n_raw < KPRE) || (n_raw > CAPG);
        s_m  = 0;
    }
    if (tid < HBINS) hist64[tid] = 0;
    sorted[tid] = 0ULL;
    __syncthreads();

    if (!s_fb) {
        for (unsigned int i = tid; i < n_raw; i += SNT) {
            float s = __uint_as_float((unsigned int)(gk[i] >> 32));
            int bin = min((int)((s - HLO) * HSCALE), HBINS - 1);
            atomicAdd(&hist64[bin], 1u);
        }
        __syncthreads();
        if (tid == 0) {
            unsigned int cum = 0;
            int kk = 0;
            for (int k = HBINS - 1; k >= 0; k--) {
                cum += hist64[k];
                if (cum >= KPRE) { kk = k; break; }
            }
            if (cum > KMAX) s_fb = 1;
            s_kk = (unsigned int)kk;
        }
        __syncthreads();
        if (!s_fb) {
            unsigned int kk = s_kk;
            for (unsigned int i = tid; i < n_raw; i += SNT) {
                unsigned long long key = gk[i];
                float s = __uint_as_float((unsigned int)(key >> 32));
                unsigned int bin =
                    (unsigned int)min((int)((s - HLO) * HSCALE), HBINS - 1);
                if (bin >= kk) {
                    unsigned int pos = atomicAdd(&s_m, 1u);
                    if (pos < KMAX) keys[pos] = key;
                }
            }
        }
        __syncthreads();
    }

    if (s_fb) {   // exact strided fallback
        for (int i = tid; i < FBINS; i += SNT) fhist[i] = 0;
        if (tid == 0) s_m = 0;
        __syncthreads();
        for (int a = tid; a < A; a += SNT) {
            float s = scores[((size_t)b * A + a) * (size_t)C + c];
            if (g_valid[(size_t)b * A + a] && s > SCORE_THR) {
                int bin = min(max((int)(s * (float)FBINS), 0), FBINS - 1);
                atomicAdd(&fhist[bin], 1u);
            }
        }
        __syncthreads();
        {
            unsigned int cs = 0;
            const int per = FBINS / SNT;
            #pragma unroll
            for (int i = 0; i < FBINS / SNT; i++) cs += fhist[tid * per + i];
            chunk[tid] = cs;
        }
        __syncthreads();
        if (tid == 0) {
            const int per = FBINS / SNT;
            unsigned int cum = 0;
            int cc;
            for (cc = SNT - 1; cc >= 0; cc--) {
                if (cum + chunk[cc] >= KPRE) break;
                cum += chunk[cc];
            }
            int kk = 0;
            if (cc >= 0) {
                int bs = cc * per;
                for (int bb = bs + per - 1; bb >= bs; bb--) {
                    cum += fhist[bb];
                    if (cum >= KPRE) { kk = bb; break; }
                }
            }
            while (cum > KMAX && kk < FBINS - 1) { cum -= fhist[kk]; kk++; }
            s_kk = (unsigned int)kk;
        }
        __syncthreads();
        unsigned int kk = s_kk;
        __syncthreads();
        for (int a = tid; a < A; a += SNT) {
            float s = scores[((size_t)b * A + a) * (size_t)C + c];
            if (g_valid[(size_t)b * A + a] && s > SCORE_THR) {
                unsigned int bin =
                    (unsigned int)min((int)(s * (float)FBINS), FBINS - 1);
                if (bin >= kk) {
                    unsigned int pos = atomicAdd(&s_m, 1u);
                    if (pos < KMAX)
                        keys[pos] =
                            ((unsigned long long)__float_as_uint(s) << 32) |
                            (unsigned long long)(0xFFFFFFFFu - (unsigned int)a);
                }
            }
        }
        __syncthreads();
    }

    // counting rank (keys distinct -> permutation)
    unsigned int m = min(s_m, (unsigned int)KMAX);
    for (unsigned int t = tid; t < m; t += SNT) {
        unsigned long long kt = keys[t];
        unsigned int r = 0;
        unsigned int j = 0;
        #pragma unroll 4
        for (; j + 4 <= m; j += 4) {
            r += (keys[j + 0] > kt);
            r += (keys[j + 1] > kt);
            r += (keys[j + 2] > kt);
            r += (keys[j + 3] > kt);
        }
        for (; j < m; j++) r += (keys[j] > kt);
        if (r < 512u) sorted[r] = kt;
    }
    __syncthreads();

    {
        unsigned long long key = sorted[tid];
        g_top[(size_t)bc * 512 + tid] = key;
        float s = __uint_as_float((unsigned int)(key >> 32));
        unsigned int aidx = 0xFFFFFFFFu - (unsigned int)(key & 0xFFFFFFFFull);
        float4 bx = make_float4(0.0f, 0.0f, 0.0f, 0.0f);
        if (s > SCORE_THR)
            bx = reinterpret_cast<const float4*>(g_boxes)[(size_t)b * A + aidx];
        g_cbox[(size_t)bc * 512 + tid]  = bx;
        g_parea[(size_t)bc * 512 + tid] =
            (bx.z - bx.x) * (bx.w - bx.y) * AREA_SCALE;
    }
}

// ---------------------------------------------------------------------------
// K4: IoU suppression bitmask. grid (BC, 16) x 128thr; warp = (row-group g,
// quarter q) via widx = blockIdx.y*4 + warp. Division-free compare.
// ---------------------------------------------------------------------------
__global__ void __launch_bounds__(128)
rn_iou(int C) {
    __shared__ float4 cbox[512];
    __shared__ float  parea[512];

    const int tid = threadIdx.x;
    const int bc  = blockIdx.x;

    for (int idx = tid; idx < 512; idx += 128) {
        cbox[idx]  = g_cbox[(size_t)bc * 512 + idx];
        parea[idx] = g_parea[(size_t)bc * 512 + idx];
    }
    __syncthreads();

    const int lane = tid & 31;
    const int widx = blockIdx.y * 4 + (tid >> 5);   // 0..63
    const int g    = widx >> 2;
    const int q    = widx & 3;
    const int i    = g * 32 + lane;
    const bool vi  = (i < KPRE);

    float4 bi  = cbox[i];
    float  pai = parea[i];

    unsigned int* __restrict__ om = g_ioum + (size_t)bc * KPRE * 16;

    int ch0 = g + ((q - g) & 3);
    for (int ch = ch0; ch < 16; ch += 4) {
        unsigned int m = 0;
        int jbase = ch * 32;
        if (ch == g) {
            #pragma unroll 8
            for (int jj = 0; jj < 32; jj++) {
                int j = jbase + jj;
                float4 bj = cbox[j];
                float lx = fmaxf(bi.x, bj.x);
                float ly = fmaxf(bi.y, bj.y);
                float rx = fminf(bi.z, bj.z);
                float ry = fminf(bi.w, bj.w);
                float inter = fmaxf(rx - lx, 0.0f) * fmaxf(ry - ly, 0.0f);
                bool pred = (j > i) && (inter > pai + parea[j]);
                m |= ((unsigned int)pred) << jj;
            }
        } else {
            #pragma unroll 8
            for (int jj = 0; jj < 32; jj++) {
                int j = jbase + jj;
                float4 bj = cbox[j];
                float lx = fmaxf(bi.x, bj.x);
                float ly = fmaxf(bi.y, bj.y);
                float rx = fminf(bi.z, bj.z);
                float ry = fminf(bi.w, bj.w);
                float inter = fmaxf(rx - lx, 0.0f) * fmaxf(ry - ly, 0.0f);
                bool pred = (inter > pai + parea[j]);
                m |= ((unsigned int)pred) << jj;
            }
        }
        if (vi) om[i * 16 + ch] = m;
    }
}

// ---------------------------------------------------------------------------
// K5: serial-semantics NMS scan (single-lane, register keep words) + output
// ---------------------------------------------------------------------------
__global__ void __launch_bounds__(512)
rn_scan(float* __restrict__ out, int B, int A, int C) {
    __shared__ unsigned int ioum[KPRE * 16];
    __shared__ float4       cbox[KPRE];
    __shared__ float        cscore[KPRE];
    __shared__ unsigned int keep0[16], keepw[16], pref[16];
    __shared__ unsigned int s_nkeep;

    const int tid = threadIdx.x;
    const int bc  = blockIdx.x;

    if (tid < 16) keep0[tid] = 0;
    {
        const uint4* __restrict__ src =
            reinterpret_cast<const uint4*>(g_ioum + (size_t)bc * KPRE * 16);
        uint4* dst = reinterpret_cast<uint4*>(ioum);
        for (int i = tid; i < KPRE * 4; i += 512) dst[i] = src[i];
    }
    if (tid < KPRE) {
        unsigned long long key = g_top[(size_t)bc * 512 + tid];
        float s = __uint_as_float((unsigned int)(key >> 32));
        bool cv = (s > SCORE_THR);
        cscore[tid] = s;
        cbox[tid]   = g_cbox[(size_t)bc * 512 + tid];
        if (cv) atomicOr(&keep0[tid >> 5], 1u << (tid & 31));
    }
    __syncthreads();

    if (tid == 0) {
        unsigned int kw[16];
        #pragma unroll
        for (int w = 0; w < 16; w++) kw[w] = keep0[w];
        int kept = 0;
        #pragma unroll
        for (int w = 0; w < 16; w++) {
            if (kept >= MAXDET) break;
            unsigned int p = 0;
            while (p < 32u && kept < MAXDET) {
                unsigned int rem = kw[w] & (0xFFFFFFFFu << p);
                if (!rem) break;
                int bit = __ffs(rem) - 1;
                int i = w * 32 + bit;
                #pragma unroll
                for (int k = 0; k < 16; k++)
                    if (k >= w) kw[k] &= ~ioum[i * 16 + k];
                kept++;
                p = (unsigned int)bit + 1u;
            }
        }
        unsigned int acc = 0;
        #pragma unroll
        for (int w = 0; w < 16; w++) {
            keepw[w] = kw[w];
            pref[w]  = acc;
            acc += __popc(kw[w]);
        }
        s_nkeep = acc;
    }
    __syncthreads();

    float* outp = out + (size_t)bc * MAXDET * 5;
    if (tid < KPRE) {
        unsigned int kw = keepw[tid >> 5];
        if ((kw >> (tid & 31)) & 1u) {
            unsigned int rank = pref[tid >> 5] + __popc(kw & ((1u << (tid & 31)) - 1u));
            if (rank < MAXDET) {
                float4 bx = cbox[tid];
                outp[rank * 5 + 0] = bx.x;
                outp[rank * 5 + 1] = bx.y;
                outp[rank * 5 + 2] = bx.z;
                outp[rank * 5 + 3] = bx.w;
                outp[rank * 5 + 4] = cscore[tid];
            }
        }
    }
    unsigned int nk = min(s_nkeep, (unsigned int)MAXDET);
    for (int r = (int)nk + tid; r < MAXDET; r += 512) {
        outp[r * 5 + 0] = 0.0f;
        outp[r * 5 + 1] = 0.0f;
        outp[r * 5 + 2] = 0.0f;
        outp[r * 5 + 3] = 0.0f;
        outp[r * 5 + 4] = -1.0f;
    }
}

// ---------------------------------------------------------------------------
// host launch
// ---------------------------------------------------------------------------
extern "C" void kernel_launch(void* const* d_in, const int* in_sizes, int n_in,
                              void* d_out, int out_size) {
    const float* deltas  = (const float*)d_in[0];
    const float* scores  = (const float*)d_in[1];
    const float* anchors = (const float*)d_in[2];
    const int*   imh     = (const int*)d_in[3];
    const int*   imw     = (const int*)d_in[4];

    long long nd = in_sizes[0];
    long long ns = in_sizes[1];
    int C  = (int)(ns * 4 / nd);
    int BC = out_size / (MAXDET * 5);
    int B  = BC / C;
    int A  = (int)(nd / (4LL * B));

    float* out = (float*)d_out;

    int n = B * A;
    rn_decode<<<(n + 255) / 256, 256>>>(deltas, anchors, imh, imw, B, A);

    dim3 cg((A + CA - 1) / CA, B);
    rn_collect<<<cg, CANT>>>(scores, B, A, C);

    cudaFuncSetAttribute(rn_sort, cudaFuncAttributeMaxDynamicSharedMemorySize, SORT_SMEM);
    rn_sort<<<BC, SNT, SORT_SMEM>>>(scores, B, A, C);
    rn_iou<<<dim3(BC, 16), 128>>>(C);
    rn_scan<<<BC, 512>>>(out, B, A, C);
}

// round 14
// speedup vs baseline: 1.1401x; 1.0138x over previous
#include <cuda_runtime.h>
#include <stdint.h>

#define KPRE       500
#define MAXDET     300
#define SCORE_THR  0.05f
#define NMS_THR    0.5f
#define MIN_SIZE   0.01f
#define BBOX_CLAMP 4.135166556742356f   // log(1000/16)
#define AREA_SCALE (NMS_THR / (1.0f + NMS_THR))   // thr/(1+thr)

#define HLO        0.99f
#define HBINS      64
#define HSCALE     6400.0f               // HBINS / (1 - HLO)
#define CAPG       16384
#define KMAX       2048
#define FBINS      8192

#define BMAX   2
#define AMAX   131072
#define CMAX   96
#define BCMAX  192

__device__ float              g_boxes[(size_t)BMAX * AMAX * 4];
__device__ unsigned char      g_valid[(size_t)BMAX * AMAX];
__device__ unsigned long long g_keys[(size_t)BCMAX * CAPG];
__device__ unsigned int       g_cnt[BCMAX];        // zero-init; each launch leaves it zero
__device__ unsigned long long g_top[(size_t)BCMAX * 512];
__device__ float4             g_cbox[(size_t)BCMAX * 512];
__device__ float              g_parea[(size_t)BCMAX * 512];
__device__ unsigned int       g_ioum[(size_t)BCMAX * KPRE * 16];

// ---------------------------------------------------------------------------
// K1 (fused): per-block decode of own anchors + score collect.
// Decode->collect dependency is block-local (validity of own anchors only).
// ---------------------------------------------------------------------------
#define CA   64      // anchors per block
#define CANT 128

__device__ __forceinline__ void rn_push_g(float s, int bc, unsigned int a) {
    unsigned int pos = atomicAdd(&g_cnt[bc], 1u);
    if (pos < CAPG)
        g_keys[(size_t)bc * CAPG + pos] =
            ((unsigned long long)__float_as_uint(s) << 32) |
            (unsigned long long)(0xFFFFFFFFu - a);
}

__global__ void __launch_bounds__(CANT)
rn_collect(const float* __restrict__ deltas,
           const float* __restrict__ anchors,
           const int* __restrict__ imh,
           const int* __restrict__ imw,
           const float* __restrict__ scores,
           int B, int A, int C) {
    __shared__ unsigned char s_val[CA];

    int b   = blockIdx.y;
    int a0  = blockIdx.x * CA;
    int na  = min(CA, A - a0);
    int tid = threadIdx.x;

    // ---- phase 1: decode this block's anchors ----
    if (tid < na) {
        int gi = b * A + a0 + tid;
        float W = (float)imw[0];
        float H = (float)imh[0];
        float4 an = reinterpret_cast<const float4*>(anchors)[gi];
        float4 dt = reinterpret_cast<const float4*>(deltas)[gi];
        float aw  = an.z - an.x;
        float ah  = an.w - an.y;
        float acx = an.x + 0.5f * aw;
        float acy = an.y + 0.5f * ah;
        float dw  = fminf(dt.z, BBOX_CLAMP);
        float dh  = fminf(dt.w, BBOX_CLAMP);
        float pcx = dt.x * aw + acx;
        float pcy = dt.y * ah + acy;
        float pw  = expf(dw) * aw;
        float ph  = expf(dh) * ah;
        float x1 = fminf(fmaxf(pcx - 0.5f * pw, 0.0f), W);
        float y1 = fminf(fmaxf(pcy - 0.5f * ph, 0.0f), H);
        float x2 = fminf(fmaxf(pcx + 0.5f * pw, 0.0f), W);
        float y2 = fminf(fmaxf(pcy + 0.5f * ph, 0.0f), H);
        reinterpret_cast<float4*>(g_boxes)[gi] = make_float4(x1, y1, x2, y2);
        unsigned char v =
            (((x2 - x1) >= MIN_SIZE) && ((y2 - y1) >= MIN_SIZE)) ? 1 : 0;
        s_val[tid]  = v;
        g_valid[gi] = v;   // kept for the exact fallback path in rn_sort
    }
    __syncthreads();

    // ---- phase 2: scan this block's scores ----
    if ((C & 3) == 0) {
        unsigned int C4 = (unsigned int)C >> 2;
        const float4* __restrict__ s4 =
            reinterpret_cast<const float4*>(scores + ((size_t)b * A + a0) * C);
        unsigned int n4 = (unsigned int)na * C4;

        auto proc = [&](float4 v, unsigned int i) {
            unsigned int a  = i / C4;
            unsigned int c4 = (i - a * C4) << 2;
            unsigned int ag = (unsigned int)a0 + a;
            if (s_val[a]) {
                int bc = b * C + (int)c4;
                if (v.x > HLO) rn_push_g(v.x, bc + 0, ag);
                if (v.y > HLO) rn_push_g(v.y, bc + 1, ag);
                if (v.z > HLO) rn_push_g(v.z, bc + 2, ag);
                if (v.w > HLO) rn_push_g(v.w, bc + 3, ag);
            }
        };

        unsigned int i = (unsigned int)tid;
        for (; i + 7u * CANT < n4; i += 8u * CANT) {
            float4 v[8];
            #pragma unroll
            for (int u = 0; u < 8; u++)
                v[u] = s4[i + (unsigned int)u * CANT];
            #pragma unroll
            for (int p = 0; p < 4; p++) {
                float4 va = v[2 * p];
                float4 vb = v[2 * p + 1];
                float m0 = fmaxf(va.x, va.y);
                float m1 = fmaxf(va.z, va.w);
                float m2 = fmaxf(vb.x, vb.y);
                float m3 = fmaxf(vb.z, vb.w);
                float m4 = fmaxf(m0, m1);
                float m5 = fmaxf(m2, m3);
                float mm = fmaxf(m4, m5);
                if (mm > HLO) {
                    unsigned int ia = i + (unsigned int)(2 * p) * CANT;
                    unsigned int ib = ia + CANT;
                    if (m4 > HLO) proc(va, ia);
                    if (m5 > HLO) proc(vb, ib);
                }
            }
        }
        for (; i < n4; i += CANT) {
            float4 va = s4[i];
            float mm = fmaxf(fmaxf(va.x, va.y), fmaxf(va.z, va.w));
            if (mm > HLO) proc(va, i);
        }
    } else {
        const float* __restrict__ s1 = scores + ((size_t)b * A + a0) * C;
        unsigned int nE = (unsigned int)na * (unsigned int)C;
        for (unsigned int i = (unsigned int)tid; i < nE; i += CANT) {
            float s = s1[i];
            if (s > HLO) {
                unsigned int a = i / (unsigned int)C;
                unsigned int c = i - a * (unsigned int)C;
                if (s_val[a])
                    rn_push_g(s, b * C + (int)c, (unsigned int)a0 + a);
            }
        }
    }
}

// ---------------------------------------------------------------------------
// K2: per-class top-512 by counting rank; epilogue gathers boxes + areas.
// Resets g_cnt[bc] to 0 at the end (keeps state zero across graph replays).
// ---------------------------------------------------------------------------
#define SNT 512
#define SORT_SMEM 49152   // [0,32768) fhist (fallback) | [32768,49152) keys[KMAX]

__global__ void __launch_bounds__(SNT)
rn_sort(const float* __restrict__ scores, int B, int A, int C) {
    extern __shared__ unsigned char dyn[];
    unsigned int*       fhist = reinterpret_cast<unsigned int*>(dyn);
    unsigned long long* keys  = reinterpret_cast<unsigned long long*>(dyn + 32768);

    __shared__ unsigned long long sorted[512];
    __shared__ unsigned int hist64[HBINS];
    __shared__ unsigned int chunk[SNT];
    __shared__ unsigned int s_m, s_kk;
    __shared__ int          s_fb;

    const int tid = threadIdx.x;
    const int bc  = blockIdx.x;
    const int b   = bc / C;
    const int c   = bc % C;

    unsigned int n_raw = g_cnt[bc];
    const unsigned long long* __restrict__ gk = g_keys + (size_t)bc * CAPG;

    if (tid == 0) {
        s_fb = (n_raw < KPRE) || (n_raw > CAPG);
        s_m  = 0;
        g_cnt[bc] = 0;                       // reset for next launch/replay
    }
    if (tid < HBINS) hist64[tid] = 0;
    sorted[tid] = 0ULL;
    __syncthreads();

    if (!s_fb) {
        for (unsigned int i = tid; i < n_raw; i += SNT) {
            float s = __uint_as_float((unsigned int)(gk[i] >> 32));
            int bin = min((int)((s - HLO) * HSCALE), HBINS - 1);
            atomicAdd(&hist64[bin], 1u);
        }
        __syncthreads();
        if (tid == 0) {
            unsigned int cum = 0;
            int kk = 0;
            for (int k = HBINS - 1; k >= 0; k--) {
                cum += hist64[k];
                if (cum >= KPRE) { kk = k; break; }
            }
            if (cum > KMAX) s_fb = 1;
            s_kk = (unsigned int)kk;
        }
        __syncthreads();
        if (!s_fb) {
            unsigned int kk = s_kk;
            for (unsigned int i = tid; i < n_raw; i += SNT) {
                unsigned long long key = gk[i];
                float s = __uint_as_float((unsigned int)(key >> 32));
                unsigned int bin =
                    (unsigned int)min((int)((s - HLO) * HSCALE), HBINS - 1);
                if (bin >= kk) {
                    unsigned int pos = atomicAdd(&s_m, 1u);
                    if (pos < KMAX) keys[pos] = key;
                }
            }
        }
        __syncthreads();
    }

    if (s_fb) {   // exact strided fallback
        for (int i = tid; i < FBINS; i += SNT) fhist[i] = 0;
        if (tid == 0) s_m = 0;
        __syncthreads();
        for (int a = tid; a < A; a += SNT) {
            float s = scores[((size_t)b * A + a) * (size_t)C + c];
            if (g_valid[(size_t)b * A + a] && s > SCORE_THR) {
                int bin = min(max((int)(s * (float)FBINS), 0), FBINS - 1);
                atomicAdd(&fhist[bin], 1u);
            }
        }
        __syncthreads();
        {
            unsigned int cs = 0;
            const int per = FBINS / SNT;
            #pragma unroll
            for (int i = 0; i < FBINS / SNT; i++) cs += fhist[tid * per + i];
            chunk[tid] = cs;
        }
        __syncthreads();
        if (tid == 0) {
            const int per = FBINS / SNT;
            unsigned int cum = 0;
            int cc;
            for (cc = SNT - 1; cc >= 0; cc--) {
                if (cum + chunk[cc] >= KPRE) break;
                cum += chunk[cc];
            }
            int kk = 0;
            if (cc >= 0) {
                int bs = cc * per;
                for (int bb = bs + per - 1; bb >= bs; bb--) {
                    cum += fhist[bb];
                    if (cum >= KPRE) { kk = bb; break; }
                }
            }
            while (cum > KMAX && kk < FBINS - 1) { cum -= fhist[kk]; kk++; }
            s_kk = (unsigned int)kk;
        }
        __syncthreads();
        unsigned int kk = s_kk;
        __syncthreads();
        for (int a = tid; a < A; a += SNT) {
            float s = scores[((size_t)b * A + a) * (size_t)C + c];
            if (g_valid[(size_t)b * A + a] && s > SCORE_THR) {
                unsigned int bin =
                    (unsigned int)min((int)(s * (float)FBINS), FBINS - 1);
                if (bin >= kk) {
                    unsigned int pos = atomicAdd(&s_m, 1u);
                    if (pos < KMAX)
                        keys[pos] =
                            ((unsigned long long)__float_as_uint(s) << 32) |
                            (unsigned long long)(0xFFFFFFFFu - (unsigned int)a);
                }
            }
        }
        __syncthreads();
    }

    // counting rank (keys distinct -> permutation)
    unsigned int m = min(s_m, (unsigned int)KMAX);
    for (unsigned int t = tid; t < m; t += SNT) {
        unsigned long long kt = keys[t];
        unsigned int r = 0;
        unsigned int j = 0;
        #pragma unroll 4
        for (; j + 4 <= m; j += 4) {
            r += (keys[j + 0] > kt);
            r += (keys[j + 1] > kt);
            r += (keys[j + 2] > kt);
            r += (keys[j + 3] > kt);
        }
        for (; j < m; j++) r += (keys[j] > kt);
        if (r < 512u) sorted[r] = kt;
    }
    __syncthreads();

    {
        unsigned long long key = sorted[tid];
        g_top[(size_t)bc * 512 + tid] = key;
        float s = __uint_as_float((unsigned int)(key >> 32));
        unsigned int aidx = 0xFFFFFFFFu - (unsigned int)(key & 0xFFFFFFFFull);
        float4 bx = make_float4(0.0f, 0.0f, 0.0f, 0.0f);
        if (s > SCORE_THR)
            bx = reinterpret_cast<const float4*>(g_boxes)[(size_t)b * A + aidx];
        g_cbox[(size_t)bc * 512 + tid]  = bx;
        g_parea[(size_t)bc * 512 + tid] =
            (bx.z - bx.x) * (bx.w - bx.y) * AREA_SCALE;
    }
}

// ---------------------------------------------------------------------------
// K3: IoU suppression bitmask. grid (BC, 16) x 128thr. Writes ZEROS for
// lower-triangle words so the scan can use clean uint4 row loads.
// ---------------------------------------------------------------------------
__global__ void __launch_bounds__(128)
rn_iou(int C) {
    __shared__ float4 cbox[512];
    __shared__ float  parea[512];

    const int tid = threadIdx.x;
    const int bc  = blockIdx.x;

    for (int idx = tid; idx < 512; idx += 128) {
        cbox[idx]  = g_cbox[(size_t)bc * 512 + idx];
        parea[idx] = g_parea[(size_t)bc * 512 + idx];
    }
    __syncthreads();

    const int lane = tid & 31;
    const int widx = blockIdx.y * 4 + (tid >> 5);   // 0..63
    const int g    = widx >> 2;
    const int q    = widx & 3;
    const int i    = g * 32 + lane;
    const bool vi  = (i < KPRE);

    float4 bi  = cbox[i];
    float  pai = parea[i];

    unsigned int* __restrict__ om = g_ioum + (size_t)bc * KPRE * 16;

    for (int ch = q; ch < 16; ch += 4) {
        unsigned int m = 0;
        int jbase = ch * 32;
        if (ch == g) {
            #pragma unroll 8
            for (int jj = 0; jj < 32; jj++) {
                int j = jbase + jj;
                float4 bj = cbox[j];
                float lx = fmaxf(bi.x, bj.x);
                float ly = fmaxf(bi.y, bj.y);
                float rx = fminf(bi.z, bj.z);
                float ry = fminf(bi.w, bj.w);
                float inter = fmaxf(rx - lx, 0.0f) * fmaxf(ry - ly, 0.0f);
                bool pred = (j > i) && (inter > pai + parea[j]);
                m |= ((unsigned int)pred) << jj;
            }
        } else if (ch > g) {
            #pragma unroll 8
            for (int jj = 0; jj < 32; jj++) {
                int j = jbase + jj;
                float4 bj = cbox[j];
                float lx = fmaxf(bi.x, bj.x);
                float ly = fmaxf(bi.y, bj.y);
                float rx = fminf(bi.z, bj.z);
                float ry = fminf(bi.w, bj.w);
                float inter = fmaxf(rx - lx, 0.0f) * fmaxf(ry - ly, 0.0f);
                bool pred = (inter > pai + parea[j]);
                m |= ((unsigned int)pred) << jj;
            }
        }
        // ch < g: m stays 0 (explicit zero for clean uint4 scan loads)
        if (vi) om[i * 16 + ch] = m;
    }
}

// ---------------------------------------------------------------------------
// K4: serial-semantics NMS scan: uint4 mask rows (4 LDS.128 per suppression),
// single-lane register keep words; ranked output.
// ---------------------------------------------------------------------------
__global__ void __launch_bounds__(512)
rn_scan(float* __restrict__ out, int B, int A, int C) {
    __shared__ uint4        ioum4[KPRE * 4];   // 32000 B, row i = ioum4[i*4..i*4+3]
    __shared__ float4       cbox[KPRE];
    __shared__ float        cscore[KPRE];
    __shared__ unsigned int keep0[16], keepw[16], pref[16];
    __shared__ unsigned int s_nkeep;

    const int tid = threadIdx.x;
    const int bc  = blockIdx.x;

    if (tid < 16) keep0[tid] = 0;
    {
        const uint4* __restrict__ src =
            reinterpret_cast<const uint4*>(g_ioum + (size_t)bc * KPRE * 16);
        for (int i = tid; i < KPRE * 4; i += 512) ioum4[i] = src[i];
    }
    if (tid < KPRE) {
        unsigned long long key = g_top[(size_t)bc * 512 + tid];
        float s = __uint_as_float((unsigned int)(key >> 32));
        bool cv = (s > SCORE_THR);
        cscore[tid] = s;
        cbox[tid]   = g_cbox[(size_t)bc * 512 + tid];
        if (cv) atomicOr(&keep0[tid >> 5], 1u << (tid & 31));
    }
    __syncthreads();

    if (tid == 0) {
        unsigned int kw[16];
        #pragma unroll
        for (int w = 0; w < 16; w++) kw[w] = keep0[w];
        int kept = 0;
        #pragma unroll
        for (int w = 0; w < 16; w++) {
            if (kept >= MAXDET) break;
            unsigned int p = 0;
            while (p < 32u && kept < MAXDET) {
                unsigned int rem = kw[w] & (0xFFFFFFFFu << p);
                if (!rem) break;
                int bit = __ffs(rem) - 1;
                int i = w * 32 + bit;
                uint4 r0 = ioum4[i * 4 + 0];
                uint4 r1 = ioum4[i * 4 + 1];
                uint4 r2 = ioum4[i * 4 + 2];
                uint4 r3 = ioum4[i * 4 + 3];
                kw[0]  &= ~r0.x;  kw[1]  &= ~r0.y;  kw[2]  &= ~r0.z;  kw[3]  &= ~r0.w;
                kw[4]  &= ~r1.x;  kw[5]  &= ~r1.y;  kw[6]  &= ~r1.z;  kw[7]  &= ~r1.w;
                kw[8]  &= ~r2.x;  kw[9]  &= ~r2.y;  kw[10] &= ~r2.z;  kw[11] &= ~r2.w;
                kw[12] &= ~r3.x;  kw[13] &= ~r3.y;  kw[14] &= ~r3.z;  kw[15] &= ~r3.w;
                kept++;
                p = (unsigned int)bit + 1u;
            }
        }
        unsigned int acc = 0;
        #pragma unroll
        for (int w = 0; w < 16; w++) {
            keepw[w] = kw[w];
            pref[w]  = acc;
            acc += __popc(kw[w]);
        }
        s_nkeep = acc;
    }
    __syncthreads();

    float* outp = out + (size_t)bc * MAXDET * 5;
    if (tid < KPRE) {
        unsigned int kw = keepw[tid >> 5];
        if ((kw >> (tid & 31)) & 1u) {
            unsigned int rank = pref[tid >> 5] + __popc(kw & ((1u << (tid & 31)) - 1u));
            if (rank < MAXDET) {
                float4 bx = cbox[tid];
                outp[rank * 5 + 0] = bx.x;
                outp[rank * 5 + 1] = bx.y;
                outp[rank * 5 + 2] = bx.z;
                outp[rank * 5 + 3] = bx.w;
                outp[rank * 5 + 4] = cscore[tid];
            }
        }
    }
    unsigned int nk = min(s_nkeep, (unsigned int)MAXDET);
    for (int r = (int)nk + tid; r < MAXDET; r += 512) {
        outp[r * 5 + 0] = 0.0f;
        outp[r * 5 + 1] = 0.0f;
        outp[r * 5 + 2] = 0.0f;
        outp[r * 5 + 3] = 0.0f;
        outp[r * 5 + 4] = -1.0f;
    }
}

// ---------------------------------------------------------------------------
// host launch (4 kernels)
// ---------------------------------------------------------------------------
extern "C" void kernel_launch(void* const* d_in, const int* in_sizes, int n_in,
                              void* d_out, int out_size) {
    const float* deltas  = (const float*)d_in[0];
    const float* scores  = (const float*)d_in[1];
    const float* anchors = (const float*)d_in[2];
    const int*   imh     = (const int*)d_in[3];
    const int*   imw     = (const int*)d_in[4];

    long long nd = in_sizes[0];
    long long ns = in_sizes[1];
    int C  = (int)(ns * 4 / nd);
    int BC = out_size / (MAXDET * 5);
    int B  = BC / C;
    int A  = (int)(nd / (4LL * B));

    float* out = (float*)d_out;

    dim3 cg((A + CA - 1) / CA, B);
    rn_collect<<<cg, CANT>>>(deltas, anchors, imh, imw, scores, B, A, C);

    cudaFuncSetAttribute(rn_sort, cudaFuncAttributeMaxDynamicSharedMemorySize, SORT_SMEM);
    rn_sort<<<BC, SNT, SORT_SMEM>>>(scores, B, A, C);
    rn_iou<<<dim3(BC, 16), 128>>>(C);
    rn_scan<<<BC, 512>>>(out, B, A, C);
}

// round 15
// speedup vs baseline: 1.1544x; 1.0125x over previous
#include <cuda_runtime.h>
#include <stdint.h>

#define KPRE       500
#define MAXDET     300
#define SCORE_THR  0.05f
#define NMS_THR    0.5f
#define MIN_SIZE   0.01f
#define BBOX_CLAMP 4.135166556742356f   // log(1000/16)
#define AREA_SCALE (NMS_THR / (1.0f + NMS_THR))   // thr/(1+thr)

#define HLO        0.99f
#define HBINS      64
#define HSCALE     6400.0f               // HBINS / (1 - HLO)
#define CAPG       16384
#define KMAX       2048
#define FBINS      8192

#define BMAX   2
#define AMAX   131072
#define CMAX   96
#define BCMAX  192

__device__ float              g_boxes[(size_t)BMAX * AMAX * 4];
__device__ unsigned char      g_valid[(size_t)BMAX * AMAX];
__device__ unsigned long long g_keys[(size_t)BCMAX * CAPG];
__device__ unsigned int       g_cnt[BCMAX];        // zero-init; each launch leaves it zero
__device__ unsigned long long g_top[(size_t)BCMAX * 512];
__device__ float4             g_cbox[(size_t)BCMAX * 512];
__device__ float              g_parea[(size_t)BCMAX * 512];
__device__ unsigned int       g_ioum[(size_t)BCMAX * KPRE * 16];

// ---------------------------------------------------------------------------
// K1 (fused): per-block decode of own anchors + score collect.
// ---------------------------------------------------------------------------
#define CA   64      // anchors per block
#define CANT 128

__device__ __forceinline__ void rn_push_g(float s, int bc, unsigned int a) {
    unsigned int pos = atomicAdd(&g_cnt[bc], 1u);
    if (pos < CAPG)
        g_keys[(size_t)bc * CAPG + pos] =
            ((unsigned long long)__float_as_uint(s) << 32) |
            (unsigned long long)(0xFFFFFFFFu - a);
}

__global__ void __launch_bounds__(CANT)
rn_collect(const float* __restrict__ deltas,
           const float* __restrict__ anchors,
           const int* __restrict__ imh,
           const int* __restrict__ imw,
           const float* __restrict__ scores,
           int B, int A, int C) {
    __shared__ unsigned char s_val[CA];

    int b   = blockIdx.y;
    int a0  = blockIdx.x * CA;
    int na  = min(CA, A - a0);
    int tid = threadIdx.x;

    // ---- phase 1: decode this block's anchors ----
    if (tid < na) {
        int gi = b * A + a0 + tid;
        float W = (float)imw[0];
        float H = (float)imh[0];
        float4 an = reinterpret_cast<const float4*>(anchors)[gi];
        float4 dt = reinterpret_cast<const float4*>(deltas)[gi];
        float aw  = an.z - an.x;
        float ah  = an.w - an.y;
        float acx = an.x + 0.5f * aw;
        float acy = an.y + 0.5f * ah;
        float dw  = fminf(dt.z, BBOX_CLAMP);
        float dh  = fminf(dt.w, BBOX_CLAMP);
        float pcx = dt.x * aw + acx;
        float pcy = dt.y * ah + acy;
        float pw  = expf(dw) * aw;
        float ph  = expf(dh) * ah;
        float x1 = fminf(fmaxf(pcx - 0.5f * pw, 0.0f), W);
        float y1 = fminf(fmaxf(pcy - 0.5f * ph, 0.0f), H);
        float x2 = fminf(fmaxf(pcx + 0.5f * pw, 0.0f), W);
        float y2 = fminf(fmaxf(pcy + 0.5f * ph, 0.0f), H);
        reinterpret_cast<float4*>(g_boxes)[gi] = make_float4(x1, y1, x2, y2);
        unsigned char v =
            (((x2 - x1) >= MIN_SIZE) && ((y2 - y1) >= MIN_SIZE)) ? 1 : 0;
        s_val[tid]  = v;
        g_valid[gi] = v;
    }
    __syncthreads();

    // ---- phase 2: scan this block's scores ----
    if ((C & 3) == 0) {
        unsigned int C4 = (unsigned int)C >> 2;
        const float4* __restrict__ s4 =
            reinterpret_cast<const float4*>(scores + ((size_t)b * A + a0) * C);
        unsigned int n4 = (unsigned int)na * C4;

        auto proc = [&](float4 v, unsigned int i) {
            unsigned int a  = i / C4;
            unsigned int c4 = (i - a * C4) << 2;
            unsigned int ag = (unsigned int)a0 + a;
            if (s_val[a]) {
                int bc = b * C + (int)c4;
                if (v.x > HLO) rn_push_g(v.x, bc + 0, ag);
                if (v.y > HLO) rn_push_g(v.y, bc + 1, ag);
                if (v.z > HLO) rn_push_g(v.z, bc + 2, ag);
                if (v.w > HLO) rn_push_g(v.w, bc + 3, ag);
            }
        };

        unsigned int i = (unsigned int)tid;
        for (; i + 7u * CANT < n4; i += 8u * CANT) {
            float4 v[8];
            #pragma unroll
            for (int u = 0; u < 8; u++)
                v[u] = s4[i + (unsigned int)u * CANT];
            #pragma unroll
            for (int p = 0; p < 4; p++) {
                float4 va = v[2 * p];
                float4 vb = v[2 * p + 1];
                float m0 = fmaxf(va.x, va.y);
                float m1 = fmaxf(va.z, va.w);
                float m2 = fmaxf(vb.x, vb.y);
                float m3 = fmaxf(vb.z, vb.w);
                float m4 = fmaxf(m0, m1);
                float m5 = fmaxf(m2, m3);
                float mm = fmaxf(m4, m5);
                if (mm > HLO) {
                    unsigned int ia = i + (unsigned int)(2 * p) * CANT;
                    unsigned int ib = ia + CANT;
                    if (m4 > HLO) proc(va, ia);
                    if (m5 > HLO) proc(vb, ib);
                }
            }
        }
        for (; i < n4; i += CANT) {
            float4 va = s4[i];
            float mm = fmaxf(fmaxf(va.x, va.y), fmaxf(va.z, va.w));
            if (mm > HLO) proc(va, i);
        }
    } else {
        const float* __restrict__ s1 = scores + ((size_t)b * A + a0) * C;
        unsigned int nE = (unsigned int)na * (unsigned int)C;
        for (unsigned int i = (unsigned int)tid; i < nE; i += CANT) {
            float s = s1[i];
            if (s > HLO) {
                unsigned int a = i / (unsigned int)C;
                unsigned int c = i - a * (unsigned int)C;
                if (s_val[a])
                    rn_push_g(s, b * C + (int)c, (unsigned int)a0 + a);
            }
        }
    }
}

// ---------------------------------------------------------------------------
// K2: per-class top-512 by counting rank; epilogue gathers boxes + areas.
// ---------------------------------------------------------------------------
#define SNT 512
#define SORT_SMEM 49152   // [0,32768) fhist (fallback) | [32768,49152) keys[KMAX]

__global__ void __launch_bounds__(SNT)
rn_sort(const float* __restrict__ scores, int B, int A, int C) {
    extern __shared__ unsigned char dyn[];
    unsigned int*       fhist = reinterpret_cast<unsigned int*>(dyn);
    unsigned long long* keys  = reinterpret_cast<unsigned long long*>(dyn + 32768);

    __shared__ unsigned long long sorted[512];
    __shared__ unsigned int hist64[HBINS];
    __shared__ unsigned int chunk[SNT];
    __shared__ unsigned int s_m, s_kk;
    __shared__ int          s_fb;

    const int tid = threadIdx.x;
    const int bc  = blockIdx.x;
    const int b   = bc / C;
    const int c   = bc % C;

    unsigned int n_raw = g_cnt[bc];
    const unsigned long long* __restrict__ gk = g_keys + (size_t)bc * CAPG;

    if (tid == 0) {
        s_fb = (n_raw < KPRE) || (n_raw > CAPG);
        s_m  = 0;
        g_cnt[bc] = 0;                       // reset for next launch/replay
    }
    if (tid < HBINS) hist64[tid] = 0;
    sorted[tid] = 0ULL;
    __syncthreads();

    if (!s_fb) {
        for (unsigned int i = tid; i < n_raw; i += SNT) {
            float s = __uint_as_float((unsigned int)(gk[i] >> 32));
            int bin = min((int)((s - HLO) * HSCALE), HBINS - 1);
            atomicAdd(&hist64[bin], 1u);
        }
        __syncthreads();
        if (tid == 0) {
            unsigned int cum = 0;
            int kk = 0;
            for (int k = HBINS - 1; k >= 0; k--) {
                cum += hist64[k];
                if (cum >= KPRE) { kk = k; break; }
            }
            if (cum > KMAX) s_fb = 1;
            s_kk = (unsigned int)kk;
        }
        __syncthreads();
        if (!s_fb) {
            unsigned int kk = s_kk;
            for (unsigned int i = tid; i < n_raw; i += SNT) {
                unsigned long long key = gk[i];
                float s = __uint_as_float((unsigned int)(key >> 32));
                unsigned int bin =
                    (unsigned int)min((int)((s - HLO) * HSCALE), HBINS - 1);
                if (bin >= kk) {
                    unsigned int pos = atomicAdd(&s_m, 1u);
                    if (pos < KMAX) keys[pos] = key;
                }
            }
        }
        __syncthreads();
    }

    if (s_fb) {   // exact strided fallback
        for (int i = tid; i < FBINS; i += SNT) fhist[i] = 0;
        if (tid == 0) s_m = 0;
        __syncthreads();
        for (int a = tid; a < A; a += SNT) {
            float s = scores[((size_t)b * A + a) * (size_t)C + c];
            if (g_valid[(size_t)b * A + a] && s > SCORE_THR) {
                int bin = min(max((int)(s * (float)FBINS), 0), FBINS - 1);
                atomicAdd(&fhist[bin], 1u);
            }
        }
        __syncthreads();
        {
            unsigned int cs = 0;
            const int per = FBINS / SNT;
            #pragma unroll
            for (int i = 0; i < FBINS / SNT; i++) cs += fhist[tid * per + i];
            chunk[tid] = cs;
        }
        __syncthreads();
        if (tid == 0) {
            const int per = FBINS / SNT;
            unsigned int cum = 0;
            int cc;
            for (cc = SNT - 1; cc >= 0; cc--) {
                if (cum + chunk[cc] >= KPRE) break;
                cum += chunk[cc];
            }
            int kk = 0;
            if (cc >= 0) {
                int bs = cc * per;
                for (int bb = bs + per - 1; bb >= bs; bb--) {
                    cum += fhist[bb];
                    if (cum >= KPRE) { kk = bb; break; }
                }
            }
            while (cum > KMAX && kk < FBINS - 1) { cum -= fhist[kk]; kk++; }
            s_kk = (unsigned int)kk;
        }
        __syncthreads();
        unsigned int kk = s_kk;
        __syncthreads();
        for (int a = tid; a < A; a += SNT) {
            float s = scores[((size_t)b * A + a) * (size_t)C + c];
            if (g_valid[(size_t)b * A + a] && s > SCORE_THR) {
                unsigned int bin =
                    (unsigned int)min((int)(s * (float)FBINS), FBINS - 1);
                if (bin >= kk) {
                    unsigned int pos = atomicAdd(&s_m, 1u);
                    if (pos < KMAX)
                        keys[pos] =
                            ((unsigned long long)__float_as_uint(s) << 32) |
                            (unsigned long long)(0xFFFFFFFFu - (unsigned int)a);
                }
            }
        }
        __syncthreads();
    }

    // counting rank (keys distinct -> permutation)
    unsigned int m = min(s_m, (unsigned int)KMAX);
    for (unsigned int t = tid; t < m; t += SNT) {
        unsigned long long kt = keys[t];
        unsigned int r = 0;
        unsigned int j = 0;
        #pragma unroll 4
        for (; j + 4 <= m; j += 4) {
            r += (keys[j + 0] > kt);
            r += (keys[j + 1] > kt);
            r += (keys[j + 2] > kt);
            r += (keys[j + 3] > kt);
        }
        for (; j < m; j++) r += (keys[j] > kt);
        if (r < 512u) sorted[r] = kt;
    }
    __syncthreads();

    {
        unsigned long long key = sorted[tid];
        g_top[(size_t)bc * 512 + tid] = key;
        float s = __uint_as_float((unsigned int)(key >> 32));
        unsigned int aidx = 0xFFFFFFFFu - (unsigned int)(key & 0xFFFFFFFFull);
        float4 bx = make_float4(0.0f, 0.0f, 0.0f, 0.0f);
        if (s > SCORE_THR)
            bx = reinterpret_cast<const float4*>(g_boxes)[(size_t)b * A + aidx];
        g_cbox[(size_t)bc * 512 + tid]  = bx;
        g_parea[(size_t)bc * 512 + tid] =
            (bx.z - bx.x) * (bx.w - bx.y) * AREA_SCALE;
    }
}

// ---------------------------------------------------------------------------
// K3: IoU suppression bitmask. grid (BC, 16) x 128thr. Zeros for
// lower-triangle words (clean uint4 scan loads).
// ---------------------------------------------------------------------------
__global__ void __launch_bounds__(128)
rn_iou(int C) {
    __shared__ float4 cbox[512];
    __shared__ float  parea[512];

    const int tid = threadIdx.x;
    const int bc  = blockIdx.x;

    for (int idx = tid; idx < 512; idx += 128) {
        cbox[idx]  = g_cbox[(size_t)bc * 512 + idx];
        parea[idx] = g_parea[(size_t)bc * 512 + idx];
    }
    __syncthreads();

    const int lane = tid & 31;
    const int widx = blockIdx.y * 4 + (tid >> 5);   // 0..63
    const int g    = widx >> 2;
    const int q    = widx & 3;
    const int i    = g * 32 + lane;
    const bool vi  = (i < KPRE);

    float4 bi  = cbox[i];
    float  pai = parea[i];

    unsigned int* __restrict__ om = g_ioum + (size_t)bc * KPRE * 16;

    for (int ch = q; ch < 16; ch += 4) {
        unsigned int m = 0;
        int jbase = ch * 32;
        if (ch == g) {
            #pragma unroll 8
            for (int jj = 0; jj < 32; jj++) {
                int j = jbase + jj;
                float4 bj = cbox[j];
                float lx = fmaxf(bi.x, bj.x);
                float ly = fmaxf(bi.y, bj.y);
                float rx = fminf(bi.z, bj.z);
                float ry = fminf(bi.w, bj.w);
                float inter = fmaxf(rx - lx, 0.0f) * fmaxf(ry - ly, 0.0f);
                bool pred = (j > i) && (inter > pai + parea[j]);
                m |= ((unsigned int)pred) << jj;
            }
        } else if (ch > g) {
            #pragma unroll 8
            for (int jj = 0; jj < 32; jj++) {
                int j = jbase + jj;
                float4 bj = cbox[j];
                float lx = fmaxf(bi.x, bj.x);
                float ly = fmaxf(bi.y, bj.y);
                float rx = fminf(bi.z, bj.z);
                float ry = fminf(bi.w, bj.w);
                float inter = fmaxf(rx - lx, 0.0f) * fmaxf(ry - ly, 0.0f);
                bool pred = (inter > pai + parea[j]);
                m |= ((unsigned int)pred) << jj;
            }
        }
        if (vi) om[i * 16 + ch] = m;
    }
}

// ---------------------------------------------------------------------------
// K4: serial-semantics NMS scan. Chain critical path = ONE scalar LDS of the
// diagonal word; full-row uint4 ANDs issued off-path (consumed at next word
// boundary, scoreboard long drained). Single-lane register keep words.
// ---------------------------------------------------------------------------
__global__ void __launch_bounds__(512)
rn_scan(float* __restrict__ out, int B, int A, int C) {
    __shared__ unsigned int ioum[KPRE * 16];   // 32000 B (also read as uint4)
    __shared__ float4       cbox[KPRE];
    __shared__ float        cscore[KPRE];
    __shared__ unsigned int keep0[16], keepw[16], pref[16];
    __shared__ unsigned int s_nkeep;

    const int tid = threadIdx.x;
    const int bc  = blockIdx.x;

    if (tid < 16) keep0[tid] = 0;
    {
        const uint4* __restrict__ src =
            reinterpret_cast<const uint4*>(g_ioum + (size_t)bc * KPRE * 16);
        uint4* dst = reinterpret_cast<uint4*>(ioum);
        for (int i = tid; i < KPRE * 4; i += 512) dst[i] = src[i];
    }
    if (tid < KPRE) {
        unsigned long long key = g_top[(size_t)bc * 512 + tid];
        float s = __uint_as_float((unsigned int)(key >> 32));
        bool cv = (s > SCORE_THR);
        cscore[tid] = s;
        cbox[tid]   = g_cbox[(size_t)bc * 512 + tid];
        if (cv) atomicOr(&keep0[tid >> 5], 1u << (tid & 31));
    }
    __syncthreads();

    if (tid == 0) {
        const uint4* __restrict__ ioum4 = reinterpret_cast<const uint4*>(ioum);
        unsigned int kw[16];
        #pragma unroll
        for (int w = 0; w < 16; w++) kw[w] = keep0[w];
        int kept = 0;
        #pragma unroll
        for (int w = 0; w < 16; w++) {
            if (kept >= MAXDET) break;
            unsigned int cur = kw[w];        // all prior row-ANDs applied
            while (cur && kept < MAXDET) {
                int bit = __ffs(cur) - 1;
                int i = w * 32 + bit;
                // ---- on critical path: scalar diagonal word only ----
                unsigned int diag = ioum[i * 16 + w];
                cur &= ~diag;
                cur &= (bit < 31) ? (0xFFFFFFFFu << (bit + 1)) : 0u;
                // ---- off critical path: full-row AND into keep words ----
                uint4 r0 = ioum4[i * 4 + 0];
                uint4 r1 = ioum4[i * 4 + 1];
                uint4 r2 = ioum4[i * 4 + 2];
                uint4 r3 = ioum4[i * 4 + 3];
                kw[0]  &= ~r0.x;  kw[1]  &= ~r0.y;  kw[2]  &= ~r0.z;  kw[3]  &= ~r0.w;
                kw[4]  &= ~r1.x;  kw[5]  &= ~r1.y;  kw[6]  &= ~r1.z;  kw[7]  &= ~r1.w;
                kw[8]  &= ~r2.x;  kw[9]  &= ~r2.y;  kw[10] &= ~r2.z;  kw[11] &= ~r2.w;
                kw[12] &= ~r3.x;  kw[13] &= ~r3.y;  kw[14] &= ~r3.z;  kw[15] &= ~r3.w;
                kept++;
            }
        }
        unsigned int acc = 0;
        #pragma unroll
        for (int w = 0; w < 16; w++) {
            keepw[w] = kw[w];
            pref[w]  = acc;
            acc += __popc(kw[w]);
        }
        s_nkeep = acc;
    }
    __syncthreads();

    float* outp = out + (size_t)bc * MAXDET * 5;
    if (tid < KPRE) {
        unsigned int kw = keepw[tid >> 5];
        if ((kw >> (tid & 31)) & 1u) {
            unsigned int rank = pref[tid >> 5] + __popc(kw & ((1u << (tid & 31)) - 1u));
            if (rank < MAXDET) {
                float4 bx = cbox[tid];
                outp[rank * 5 + 0] = bx.x;
                outp[rank * 5 + 1] = bx.y;
                outp[rank * 5 + 2] = bx.z;
                outp[rank * 5 + 3] = bx.w;
                outp[rank * 5 + 4] = cscore[tid];
            }
        }
    }
    unsigned int nk = min(s_nkeep, (unsigned int)MAXDET);
    for (int r = (int)nk + tid; r < MAXDET; r += 512) {
        outp[r * 5 + 0] = 0.0f;
        outp[r * 5 + 1] = 0.0f;
        outp[r * 5 + 2] = 0.0f;
        outp[r * 5 + 3] = 0.0f;
        outp[r * 5 + 4] = -1.0f;
    }
}

// ---------------------------------------------------------------------------
// host launch (4 kernels)
// ---------------------------------------------------------------------------
extern "C" void kernel_launch(void* const* d_in, const int* in_sizes, int n_in,
                              void* d_out, int out_size) {
    const float* deltas  = (const float*)d_in[0];
    const float* scores  = (const float*)d_in[1];
    const float* anchors = (const float*)d_in[2];
    const int*   imh     = (const int*)d_in[3];
    const int*   imw     = (const int*)d_in[4];

    long long nd = in_sizes[0];
    long long ns = in_sizes[1];
    int C  = (int)(ns * 4 / nd);
    int BC = out_size / (MAXDET * 5);
    int B  = BC / C;
    int A  = (int)(nd / (4LL * B));

    float* out = (float*)d_out;

    dim3 cg((A + CA - 1) / CA, B);
    rn_collect<<<cg, CANT>>>(deltas, anchors, imh, imw, scores, B, A, C);

    cudaFuncSetAttribute(rn_sort, cudaFuncAttributeMaxDynamicSharedMemorySize, SORT_SMEM);
    rn_sort<<<BC, SNT, SORT_SMEM>>>(scores, B, A, C);
    rn_iou<<<dim3(BC, 16), 128>>>(C);
    rn_scan<<<BC, 512>>>(out, B, A, C);
}